// round 1
// baseline (speedup 1.0000x reference)
#include <cuda_runtime.h>
#include <math.h>

// Problem dims
#define BB   4
#define SS   1024
#define DD   1024
#define HH   16
#define DH   64
#define RR   64
#define DFFN 4096
#define NTOK (BB*SS)       // 4096
#define KSEL 204           // int(1024*0.2)

// ---------------- scratch (device globals; no allocation allowed) ----------------
__device__ float g_qkv[NTOK * 3 * DD];    // [4096, 3072]
__device__ float g_ctx[NTOK * DD];
__device__ float g_dense[NTOK * DD];
__device__ float g_Qlr[NTOK * RR];
__device__ float g_Klr[NTOK * RR];
__device__ float g_Vlr[NTOK * DD];
__device__ float g_P[(long)BB * SS * SS]; // scores -> sparse probs (in place)
__device__ float g_sparse[NTOK * DD];
__device__ float g_x[NTOK * DD];
__device__ float g_h1[NTOK * DFFN];
__device__ float g_ff[NTOK * DD];

// ---------------- generic tiled SGEMM: C = alpha * A(MxK) * B^T(NxK) + bias ----------------
#define BM 64
#define BN 64
#define BK 16

__global__ __launch_bounds__(256) void gemm_nt_kernel(
    const float* __restrict__ A, const float* __restrict__ B,
    const float* __restrict__ bias, float* __restrict__ C,
    int M, int N, int K, long sA, long sB, long sC, float alpha, int relu)
{
    A += (long)blockIdx.z * sA;
    B += (long)blockIdx.z * sB;
    C += (long)blockIdx.z * sC;

    __shared__ float As[BK][BM + 4];
    __shared__ float Bs[BK][BN + 4];

    const int t  = threadIdx.x;
    const int tx = t & 15, ty = t >> 4;
    const int row0 = blockIdx.y * BM, col0 = blockIdx.x * BN;

    // load mapping: thread t reads one float4; row = t>>2, kcol = (t&3)*4
    const int lr = t >> 2, lc = (t & 3) * 4;
    const float* Ap = A + (long)(row0 + lr) * K + lc;
    const float* Bp = B + (long)(col0 + lr) * K + lc;

    float acc[4][4] = {};

    for (int k0 = 0; k0 < K; k0 += BK) {
        float4 av = *(const float4*)(Ap + k0);
        float4 bv = *(const float4*)(Bp + k0);
        As[lc + 0][lr] = av.x; As[lc + 1][lr] = av.y;
        As[lc + 2][lr] = av.z; As[lc + 3][lr] = av.w;
        Bs[lc + 0][lr] = bv.x; Bs[lc + 1][lr] = bv.y;
        Bs[lc + 2][lr] = bv.z; Bs[lc + 3][lr] = bv.w;
        __syncthreads();
#pragma unroll
        for (int kk = 0; kk < BK; kk++) {
            float4 a4 = *(const float4*)&As[kk][ty * 4];
            float4 b4 = *(const float4*)&Bs[kk][tx * 4];
            float a[4] = {a4.x, a4.y, a4.z, a4.w};
            float b[4] = {b4.x, b4.y, b4.z, b4.w};
#pragma unroll
            for (int i = 0; i < 4; i++)
#pragma unroll
                for (int j = 0; j < 4; j++)
                    acc[i][j] += a[i] * b[j];
        }
        __syncthreads();
    }

    float bvv[4] = {0.f, 0.f, 0.f, 0.f};
    if (bias) {
        float4 bb4 = *(const float4*)&bias[col0 + tx * 4];
        bvv[0] = bb4.x; bvv[1] = bb4.y; bvv[2] = bb4.z; bvv[3] = bb4.w;
    }
#pragma unroll
    for (int i = 0; i < 4; i++) {
        float4 o;
        float v0 = acc[i][0] * alpha + bvv[0];
        float v1 = acc[i][1] * alpha + bvv[1];
        float v2 = acc[i][2] * alpha + bvv[2];
        float v3 = acc[i][3] * alpha + bvv[3];
        if (relu) { v0 = fmaxf(v0, 0.f); v1 = fmaxf(v1, 0.f); v2 = fmaxf(v2, 0.f); v3 = fmaxf(v3, 0.f); }
        o.x = v0; o.y = v1; o.z = v2; o.w = v3;
        *(float4*)&C[(long)(row0 + ty * 4 + i) * N + col0 + tx * 4] = o;
    }
}

// ---------------- C = A(MxK) * B(KxN), no bias ----------------
__global__ __launch_bounds__(256) void gemm_nn_kernel(
    const float* __restrict__ A, const float* __restrict__ B,
    float* __restrict__ C,
    int M, int N, int K, long sA, long sB, long sC)
{
    A += (long)blockIdx.z * sA;
    B += (long)blockIdx.z * sB;
    C += (long)blockIdx.z * sC;

    __shared__ float As[BK][BM + 4];
    __shared__ float Bs[BK][BN + 4];

    const int t  = threadIdx.x;
    const int tx = t & 15, ty = t >> 4;
    const int row0 = blockIdx.y * BM, col0 = blockIdx.x * BN;

    const int lr = t >> 2, lc = (t & 3) * 4;     // A tile 64x16
    const int bkr = t >> 4, bnc = (t & 15) * 4;  // B tile 16x64
    const float* Ap = A + (long)(row0 + lr) * K + lc;
    const float* Bp = B + (long)bkr * N + col0 + bnc;

    float acc[4][4] = {};

    for (int k0 = 0; k0 < K; k0 += BK) {
        float4 av = *(const float4*)(Ap + k0);
        As[lc + 0][lr] = av.x; As[lc + 1][lr] = av.y;
        As[lc + 2][lr] = av.z; As[lc + 3][lr] = av.w;
        float4 bv = *(const float4*)(Bp + (long)k0 * N);
        *(float4*)&Bs[bkr][bnc] = bv;
        __syncthreads();
#pragma unroll
        for (int kk = 0; kk < BK; kk++) {
            float4 a4 = *(const float4*)&As[kk][ty * 4];
            float4 b4 = *(const float4*)&Bs[kk][tx * 4];
            float a[4] = {a4.x, a4.y, a4.z, a4.w};
            float b[4] = {b4.x, b4.y, b4.z, b4.w};
#pragma unroll
            for (int i = 0; i < 4; i++)
#pragma unroll
                for (int j = 0; j < 4; j++)
                    acc[i][j] += a[i] * b[j];
        }
        __syncthreads();
    }
#pragma unroll
    for (int i = 0; i < 4; i++) {
        float4 o = {acc[i][0], acc[i][1], acc[i][2], acc[i][3]};
        *(float4*)&C[(long)(row0 + ty * 4 + i) * N + col0 + tx * 4] = o;
    }
}

// ---------------- dense multi-head attention (flash-style online softmax) ----------------
// grid: (S/128, H, B), block: 128 threads, one query per thread, dh = 64
__global__ __launch_bounds__(128) void attn_kernel(const float* __restrict__ qkv,
                                                   float* __restrict__ ctx)
{
    const int qi = blockIdx.x * 128 + threadIdx.x;
    const int h  = blockIdx.y;
    const int b  = blockIdx.z;
    const float scale = 0.125f; // 1/sqrt(64)

    __shared__ float ks[64][64];
    __shared__ float vs[64][64];

    const float* qptr = qkv + ((long)(b * SS + qi)) * (3 * DD) + h * DH;
    float q[DH];
#pragma unroll
    for (int d = 0; d < DH; d += 4) {
        float4 v = *(const float4*)(qptr + d);
        q[d] = v.x; q[d + 1] = v.y; q[d + 2] = v.z; q[d + 3] = v.w;
    }

    float m = -1e30f, l = 0.f;
    float acc[DH];
#pragma unroll
    for (int d = 0; d < DH; d++) acc[d] = 0.f;

    for (int k0 = 0; k0 < SS; k0 += 64) {
        __syncthreads();
        for (int i = threadIdx.x; i < 64 * 16; i += 128) {
            int r = i >> 4, c4 = i & 15;
            const float* kp = qkv + ((long)(b * SS + k0 + r)) * (3 * DD) + DD + h * DH + c4 * 4;
            ((float4*)&ks[r][0])[c4] = *(const float4*)kp;
            ((float4*)&vs[r][0])[c4] = *(const float4*)(kp + DD);
        }
        __syncthreads();
#pragma unroll 4
        for (int j = 0; j < 64; j++) {
            float s = 0.f;
#pragma unroll
            for (int d = 0; d < DH; d++) s += q[d] * ks[j][d];
            s *= scale;
            float mn = fmaxf(m, s);
            float corr = __expf(m - mn);
            float p = __expf(s - mn);
            l = l * corr + p;
#pragma unroll
            for (int d = 0; d < DH; d++) acc[d] = acc[d] * corr + p * vs[j][d];
            m = mn;
        }
    }
    float inv = 1.f / l;
    float* cp = ctx + ((long)(b * SS + qi)) * DD + h * DH;
#pragma unroll
    for (int d = 0; d < DH; d += 4) {
        float4 o = {acc[d] * inv, acc[d + 1] * inv, acc[d + 2] * inv, acc[d + 3] * inv};
        *(float4*)(cp + d) = o;
    }
}

// ---------------- top-k threshold + masked softmax (in-place on scores) ----------------
// one block (1024 threads) per row; bitonic-sort ascending, threshold = 204th largest
__global__ __launch_bounds__(1024) void topk_softmax_kernel(float* __restrict__ P)
{
    const long row = (long)blockIdx.x * SS;
    __shared__ float srt[SS];
    __shared__ float r1[32], r2[32];
    const int t = threadIdx.x;

    const float val = P[row + t];
    srt[t] = val;
    __syncthreads();

    for (int k = 2; k <= SS; k <<= 1) {
        for (int j = k >> 1; j > 0; j >>= 1) {
            int ixj = t ^ j;
            if (ixj > t) {
                float a = srt[t], c = srt[ixj];
                bool up = ((t & k) == 0);
                if ((a > c) == up) { srt[t] = c; srt[ixj] = a; }
            }
            __syncthreads();
        }
    }

    const float thr = srt[SS - KSEL];
    const float mx  = srt[SS - 1];

    const float efull = __expf(val - mx);
    const float ekeep = (val >= thr) ? efull : 0.f;

    float sk = ekeep, sf = efull;
#pragma unroll
    for (int o = 16; o > 0; o >>= 1) {
        sk += __shfl_xor_sync(0xffffffffu, sk, o);
        sf += __shfl_xor_sync(0xffffffffu, sf, o);
    }
    const int w = t >> 5, lane = t & 31;
    if (lane == 0) { r1[w] = sk; r2[w] = sf; }
    __syncthreads();
    if (t == 0) {
        float a = 0.f, c = 0.f;
        for (int i = 0; i < 32; i++) { a += r1[i]; c += r2[i]; }
        r1[0] = a; r2[0] = c;
    }
    __syncthreads();
    const float denom = r1[0] + 1e-9f * r2[0];   // matches ref: sum_kept + 1e-9*Z
    P[row + t] = ekeep / denom;
}

// ---------------- fuse + residual + layernorm 1 ----------------
__global__ __launch_bounds__(256) void fuse_ln1_kernel(
    const float* __restrict__ src, const float* __restrict__ dense,
    const float* __restrict__ sparse, const float* __restrict__ lam,
    const float* __restrict__ g, const float* __restrict__ bb,
    float* __restrict__ x)
{
    const long row = (long)blockIdx.x * DD;
    __shared__ float buf[DD];
    __shared__ float r1[8], r2[8];
    const float sig = 1.f / (1.f + __expf(-lam[0]));
    const float osig = 1.f - sig;

    float s1 = 0.f, s2 = 0.f;
    for (int d = threadIdx.x; d < DD; d += 256) {
        float v = src[row + d] + sig * dense[row + d] + osig * sparse[row + d];
        buf[d] = v; s1 += v; s2 += v * v;
    }
#pragma unroll
    for (int o = 16; o > 0; o >>= 1) {
        s1 += __shfl_xor_sync(0xffffffffu, s1, o);
        s2 += __shfl_xor_sync(0xffffffffu, s2, o);
    }
    const int w = threadIdx.x >> 5, lane = threadIdx.x & 31;
    if (lane == 0) { r1[w] = s1; r2[w] = s2; }
    __syncthreads();
    if (threadIdx.x == 0) {
        float a = 0.f, c = 0.f;
        for (int i = 0; i < 8; i++) { a += r1[i]; c += r2[i]; }
        r1[0] = a; r2[0] = c;
    }
    __syncthreads();
    const float mean = r1[0] * (1.f / DD);
    const float var  = r2[0] * (1.f / DD) - mean * mean;
    const float rstd = rsqrtf(var + 1e-5f);
    for (int d = threadIdx.x; d < DD; d += 256)
        x[row + d] = (buf[d] - mean) * rstd * g[d] + bb[d];
}

// ---------------- residual + layernorm 2 -> output ----------------
__global__ __launch_bounds__(256) void ln2_kernel(
    const float* __restrict__ x, const float* __restrict__ ff,
    const float* __restrict__ g, const float* __restrict__ bb,
    float* __restrict__ out)
{
    const long row = (long)blockIdx.x * DD;
    __shared__ float buf[DD];
    __shared__ float r1[8], r2[8];

    float s1 = 0.f, s2 = 0.f;
    for (int d = threadIdx.x; d < DD; d += 256) {
        float v = x[row + d] + ff[row + d];
        buf[d] = v; s1 += v; s2 += v * v;
    }
#pragma unroll
    for (int o = 16; o > 0; o >>= 1) {
        s1 += __shfl_xor_sync(0xffffffffu, s1, o);
        s2 += __shfl_xor_sync(0xffffffffu, s2, o);
    }
    const int w = threadIdx.x >> 5, lane = threadIdx.x & 31;
    if (lane == 0) { r1[w] = s1; r2[w] = s2; }
    __syncthreads();
    if (threadIdx.x == 0) {
        float a = 0.f, c = 0.f;
        for (int i = 0; i < 8; i++) { a += r1[i]; c += r2[i]; }
        r1[0] = a; r2[0] = c;
    }
    __syncthreads();
    const float mean = r1[0] * (1.f / DD);
    const float var  = r2[0] * (1.f / DD) - mean * mean;
    const float rstd = rsqrtf(var + 1e-5f);
    for (int d = threadIdx.x; d < DD; d += 256)
        out[row + d] = (buf[d] - mean) * rstd * g[d] + bb[d];
}

// ---------------- launch ----------------
extern "C" void kernel_launch(void* const* d_in, const int* in_sizes, int n_in,
                              void* d_out, int out_size)
{
    (void)in_sizes; (void)n_in; (void)out_size;
    const float* src    = (const float*)d_in[0];
    const float* in_w   = (const float*)d_in[1];
    const float* in_b   = (const float*)d_in[2];
    const float* outp_w = (const float*)d_in[3];
    const float* outp_b = (const float*)d_in[4];
    const float* Qp_w   = (const float*)d_in[5];
    const float* Qp_b   = (const float*)d_in[6];
    const float* Kp_w   = (const float*)d_in[7];
    const float* Kp_b   = (const float*)d_in[8];
    const float* Vp_w   = (const float*)d_in[9];
    const float* Vp_b   = (const float*)d_in[10];
    const float* lam    = (const float*)d_in[11];
    const float* ff1_w  = (const float*)d_in[12];
    const float* ff1_b  = (const float*)d_in[13];
    const float* ff2_w  = (const float*)d_in[14];
    const float* ff2_b  = (const float*)d_in[15];
    const float* ln1_g  = (const float*)d_in[16];
    const float* ln1_b  = (const float*)d_in[17];
    const float* ln2_g  = (const float*)d_in[18];
    const float* ln2_b  = (const float*)d_in[19];
    float* out = (float*)d_out;

    float *qkv, *ctx, *dense, *Qlr, *Klr, *Vlr, *P, *sparse, *x, *h1, *ff;
    cudaGetSymbolAddress((void**)&qkv,    g_qkv);
    cudaGetSymbolAddress((void**)&ctx,    g_ctx);
    cudaGetSymbolAddress((void**)&dense,  g_dense);
    cudaGetSymbolAddress((void**)&Qlr,    g_Qlr);
    cudaGetSymbolAddress((void**)&Klr,    g_Klr);
    cudaGetSymbolAddress((void**)&Vlr,    g_Vlr);
    cudaGetSymbolAddress((void**)&P,      g_P);
    cudaGetSymbolAddress((void**)&sparse, g_sparse);
    cudaGetSymbolAddress((void**)&x,      g_x);
    cudaGetSymbolAddress((void**)&h1,     g_h1);
    cudaGetSymbolAddress((void**)&ff,     g_ff);

    // 1. qkv = src @ in_proj_w^T + b           [4096, 3072]
    gemm_nt_kernel<<<dim3(3 * DD / BN, NTOK / BM), 256>>>(
        src, in_w, in_b, qkv, NTOK, 3 * DD, DD, 0, 0, 0, 1.f, 0);
    // 2. dense attention -> ctx                [4096, 1024]
    attn_kernel<<<dim3(SS / 128, HH, BB), 128>>>(qkv, ctx);
    // 3. dense_output = ctx @ out_proj^T + b
    gemm_nt_kernel<<<dim3(DD / BN, NTOK / BM), 256>>>(
        ctx, outp_w, outp_b, dense, NTOK, DD, DD, 0, 0, 0, 1.f, 0);
    // 4-6. low-rank projections
    gemm_nt_kernel<<<dim3(RR / BN, NTOK / BM), 256>>>(
        src, Qp_w, Qp_b, Qlr, NTOK, RR, DD, 0, 0, 0, 1.f, 0);
    gemm_nt_kernel<<<dim3(RR / BN, NTOK / BM), 256>>>(
        src, Kp_w, Kp_b, Klr, NTOK, RR, DD, 0, 0, 0, 1.f, 0);
    gemm_nt_kernel<<<dim3(DD / BN, NTOK / BM), 256>>>(
        src, Vp_w, Vp_b, Vlr, NTOK, DD, DD, 0, 0, 0, 1.f, 0);
    // 7. P = (Q @ K^T) / sqrt(R)  per batch    [B, 1024, 1024]
    gemm_nt_kernel<<<dim3(SS / BN, SS / BM, BB), 256>>>(
        Qlr, Klr, nullptr, P, SS, SS, RR,
        (long)SS * RR, (long)SS * RR, (long)SS * SS, 0.125f, 0);
    // 8. top-k threshold + masked softmax (in place)
    topk_softmax_kernel<<<NTOK, 1024>>>(P);
    // 9. sparse_output = P @ V  per batch
    gemm_nn_kernel<<<dim3(DD / BN, SS / BM, BB), 256>>>(
        P, Vlr, sparse, SS, DD, SS,
        (long)SS * SS, (long)SS * DD, (long)SS * DD);
    // 10. x = LN1(src + sig*dense + (1-sig)*sparse)
    fuse_ln1_kernel<<<NTOK, 256>>>(src, dense, sparse, lam, ln1_g, ln1_b, x);
    // 11. h1 = relu(x @ ff1^T + b)             [4096, 4096]
    gemm_nt_kernel<<<dim3(DFFN / BN, NTOK / BM), 256>>>(
        x, ff1_w, ff1_b, h1, NTOK, DFFN, DD, 0, 0, 0, 1.f, 1);
    // 12. ff = h1 @ ff2^T + b                  [4096, 1024]
    gemm_nt_kernel<<<dim3(DD / BN, NTOK / BM), 256>>>(
        h1, ff2_w, ff2_b, ff, NTOK, DD, DFFN, 0, 0, 0, 1.f, 0);
    // 13. out = LN2(x + ff)
    ln2_kernel<<<NTOK, 256>>>(x, ff, ln2_g, ln2_b, out);
}

// round 3
// speedup vs baseline: 2.2661x; 2.2661x over previous
#include <cuda_runtime.h>
#include <cstdint>
#include <math.h>

// Problem dims
#define BB   4
#define SS   1024
#define DD   1024
#define HH   16
#define DH   64
#define RR   64
#define DFFN 4096
#define NTOK (BB*SS)       // 4096
#define KSEL 204           // int(1024*0.2)

// ---------------- scratch (device globals; no allocation allowed) ----------------
__device__ float g_qkv[(long)NTOK * 3 * DD];
__device__ float g_ctx[(long)NTOK * DD];
__device__ float g_dense[(long)NTOK * DD];
__device__ float g_Qlr[NTOK * RR];
__device__ float g_Klr[NTOK * RR];
__device__ float g_Vlr[(long)NTOK * DD];
__device__ float g_Vt[(long)NTOK * DD];
__device__ float g_P[(long)BB * SS * SS];
__device__ float g_sparse[(long)NTOK * DD];
__device__ float g_x[(long)NTOK * DD];
__device__ float g_h1[(long)NTOK * DFFN];
__device__ float g_ff[(long)NTOK * DD];

// ======================= helpers =======================
__device__ __forceinline__ uint32_t smem_u32(const void* p) {
    uint32_t a;
    asm("{ .reg .u64 t; cvta.to.shared.u64 t, %1; cvt.u32.u64 %0, t; }" : "=r"(a) : "l"(p));
    return a;
}
__device__ __forceinline__ uint32_t f2tf32(float f) {
    uint32_t u; asm("cvt.rna.tf32.f32 %0, %1;" : "=r"(u) : "f"(f)); return u;
}
__device__ __forceinline__ void cp16(uint32_t saddr, const void* g, int src_sz) {
    asm volatile("cp.async.ca.shared.global [%0], [%1], 16, %2;"
                 :: "r"(saddr), "l"(g), "r"(src_sz) : "memory");
}
#define CP_COMMIT() asm volatile("cp.async.commit_group;" ::: "memory")
#define CP_WAIT1()  asm volatile("cp.async.wait_group 1;" ::: "memory")
#define CP_WAIT0()  asm volatile("cp.async.wait_group 0;" ::: "memory")

__device__ __forceinline__ void mma_tf32(float* c, const uint32_t* a, const uint32_t* b) {
    asm volatile(
        "mma.sync.aligned.m16n8k8.row.col.f32.tf32.tf32.f32 "
        "{%0,%1,%2,%3}, {%4,%5,%6,%7}, {%8,%9}, {%0,%1,%2,%3};"
        : "+f"(c[0]), "+f"(c[1]), "+f"(c[2]), "+f"(c[3])
        : "r"(a[0]), "r"(a[1]), "r"(a[2]), "r"(a[3]), "r"(b[0]), "r"(b[1]));
}

// ======================= tf32 warp-MMA GEMM: C = alpha*A(MxK)*B^T(NxK)+bias =======================
// CTA tile 128x128x16, 8 warps (2x4), warp tile 64x32. Double-buffered cp.async.
#define BM 128
#define BN 128
#define BK 16
#define KSTR 20   // padded float stride (conflict-free quad loads)

__global__ __launch_bounds__(256) void mma_gemm_nt(
    const float* __restrict__ A, const float* __restrict__ B,
    const float* __restrict__ bias, float* __restrict__ C,
    int N, int K, long sA, long sB, long sC, float alpha, int relu)
{
    __shared__ float As[2][BM * KSTR];
    __shared__ float Bs[2][BN * KSTR];

    A += (long)blockIdx.z * sA;
    B += (long)blockIdx.z * sB;
    C += (long)blockIdx.z * sC;

    const int t = threadIdx.x;
    const int wid = t >> 5, l = t & 31;
    const int wm = wid >> 2, wn = wid & 3;        // 2 x 4 warp grid
    const int mbase = wm * 64, nbase = wn * 32;
    const int qr = l >> 2, qc = l & 3;
    const int row0 = blockIdx.y * BM, col0 = blockIdx.x * BN;

    const uint32_t sA0 = smem_u32(&As[0][0]);
    const uint32_t sB0 = smem_u32(&Bs[0][0]);

    // per-thread load mapping: 2 float4 for A, 2 for B per stage
    const int lm0 = t >> 2;                 // 0..63
    const int lkc = (t & 3) * 4;            // 0,4,8,12

    float acc[4][4][4];
#pragma unroll
    for (int i = 0; i < 4; i++)
#pragma unroll
        for (int j = 0; j < 4; j++)
#pragma unroll
            for (int q = 0; q < 4; q++) acc[i][j][q] = 0.f;

    const int nc = K / BK;

    // ---- prefetch stage 0 ----
    {
        const int k0 = 0;
#pragma unroll
        for (int j = 0; j < 2; j++) {
            int m = lm0 + j * 64;
            cp16(sA0 + (m * KSTR + lkc) * 4, &A[(long)(row0 + m) * K + k0 + lkc], 16);
        }
#pragma unroll
        for (int j = 0; j < 2; j++) {
            int n = lm0 + j * 64;
            bool v = (col0 + n) < N;
            const float* gp = v ? &B[(long)(col0 + n) * K + k0 + lkc] : B;
            cp16(sB0 + (n * KSTR + lkc) * 4, gp, v ? 16 : 0);
        }
        CP_COMMIT();
    }

    for (int c = 0; c < nc; c++) {
        if (c + 1 < nc) {
            const int ns = (c + 1) & 1;
            const int k0 = (c + 1) * BK;
            const uint32_t sAs = sA0 + ns * (BM * KSTR * 4);
            const uint32_t sBs = sB0 + ns * (BN * KSTR * 4);
#pragma unroll
            for (int j = 0; j < 2; j++) {
                int m = lm0 + j * 64;
                cp16(sAs + (m * KSTR + lkc) * 4, &A[(long)(row0 + m) * K + k0 + lkc], 16);
            }
#pragma unroll
            for (int j = 0; j < 2; j++) {
                int n = lm0 + j * 64;
                bool v = (col0 + n) < N;
                const float* gp = v ? &B[(long)(col0 + n) * K + k0 + lkc] : B;
                cp16(sBs + (n * KSTR + lkc) * 4, gp, v ? 16 : 0);
            }
            CP_COMMIT();
            CP_WAIT1();
        } else {
            CP_WAIT0();
        }
        __syncthreads();

        const float* as = &As[c & 1][0];
        const float* bs = &Bs[c & 1][0];
#pragma unroll
        for (int kk = 0; kk < 2; kk++) {
            const int ks = kk * 8;
            uint32_t af[4][4], bf[4][2];
#pragma unroll
            for (int mt = 0; mt < 4; mt++) {
                const int r = mbase + mt * 16 + qr;
                af[mt][0] = f2tf32(as[r * KSTR + ks + qc]);
                af[mt][1] = f2tf32(as[(r + 8) * KSTR + ks + qc]);
                af[mt][2] = f2tf32(as[r * KSTR + ks + qc + 4]);
                af[mt][3] = f2tf32(as[(r + 8) * KSTR + ks + qc + 4]);
            }
#pragma unroll
            for (int nt = 0; nt < 4; nt++) {
                const int n = nbase + nt * 8 + qr;
                bf[nt][0] = f2tf32(bs[n * KSTR + ks + qc]);
                bf[nt][1] = f2tf32(bs[n * KSTR + ks + qc + 4]);
            }
#pragma unroll
            for (int mt = 0; mt < 4; mt++)
#pragma unroll
                for (int nt = 0; nt < 4; nt++)
                    mma_tf32(acc[mt][nt], af[mt], bf[nt]);
        }
        __syncthreads();
    }

    // ---- epilogue ----
#pragma unroll
    for (int mt = 0; mt < 4; mt++) {
        const int r = row0 + mbase + mt * 16 + qr;
#pragma unroll
        for (int nt = 0; nt < 4; nt++) {
            const int cc = col0 + nbase + nt * 8 + qc * 2;
            if (cc < N) {
                float b0 = 0.f, b1 = 0.f;
                if (bias) { b0 = bias[cc]; b1 = bias[cc + 1]; }
                float v0 = acc[mt][nt][0] * alpha + b0;
                float v1 = acc[mt][nt][1] * alpha + b1;
                float v2 = acc[mt][nt][2] * alpha + b0;
                float v3 = acc[mt][nt][3] * alpha + b1;
                if (relu) {
                    v0 = fmaxf(v0, 0.f); v1 = fmaxf(v1, 0.f);
                    v2 = fmaxf(v2, 0.f); v3 = fmaxf(v3, 0.f);
                }
                float2 p0 = {v0, v1}, p1 = {v2, v3};
                *(float2*)&C[(long)r * N + cc] = p0;
                *(float2*)&C[(long)(r + 8) * N + cc] = p1;
            }
        }
    }
}

// ======================= transpose: Vt[b][d][s] = V[b][s][d] =======================
__global__ __launch_bounds__(256) void transpose_kernel(const float* __restrict__ V,
                                                        float* __restrict__ Vt)
{
    __shared__ float tile[32][33];
    const float* Vb = V + (long)blockIdx.z * SS * DD;
    float* Vtb = Vt + (long)blockIdx.z * SS * DD;
    const int s0 = blockIdx.x * 32, d0 = blockIdx.y * 32;
    const int tx = threadIdx.x & 31, ty0 = threadIdx.x >> 5;
#pragma unroll
    for (int i = 0; i < 4; i++) {
        int ty = ty0 + i * 8;
        tile[ty][tx] = Vb[(long)(s0 + ty) * DD + d0 + tx];
    }
    __syncthreads();
#pragma unroll
    for (int i = 0; i < 4; i++) {
        int ty = ty0 + i * 8;
        Vtb[(long)(d0 + ty) * SS + s0 + tx] = tile[tx][ty];
    }
}

// ======================= dense MHA (flash-style, SIMT fp32) =======================
__global__ __launch_bounds__(128) void attn_kernel(const float* __restrict__ qkv,
                                                   float* __restrict__ ctx)
{
    const int qi = blockIdx.x * 128 + threadIdx.x;
    const int h = blockIdx.y;
    const int b = blockIdx.z;
    const float scale = 0.125f;

    __shared__ float ks[64][64];
    __shared__ float vs[64][64];

    const float* qptr = qkv + ((long)(b * SS + qi)) * (3 * DD) + h * DH;
    float q[DH];
#pragma unroll
    for (int d = 0; d < DH; d += 4) {
        float4 v = *(const float4*)(qptr + d);
        q[d] = v.x; q[d + 1] = v.y; q[d + 2] = v.z; q[d + 3] = v.w;
    }

    float m = -1e30f, l = 0.f;
    float acc[DH];
#pragma unroll
    for (int d = 0; d < DH; d++) acc[d] = 0.f;

    for (int k0 = 0; k0 < SS; k0 += 64) {
        __syncthreads();
        for (int i = threadIdx.x; i < 64 * 16; i += 128) {
            int r = i >> 4, c4 = i & 15;
            const float* kp = qkv + ((long)(b * SS + k0 + r)) * (3 * DD) + DD + h * DH + c4 * 4;
            ((float4*)&ks[r][0])[c4] = *(const float4*)kp;
            ((float4*)&vs[r][0])[c4] = *(const float4*)(kp + DD);
        }
        __syncthreads();
#pragma unroll 4
        for (int j = 0; j < 64; j++) {
            float s = 0.f;
#pragma unroll
            for (int d = 0; d < DH; d++) s += q[d] * ks[j][d];
            s *= scale;
            float mn = fmaxf(m, s);
            float corr = __expf(m - mn);
            float p = __expf(s - mn);
            l = l * corr + p;
#pragma unroll
            for (int d = 0; d < DH; d++) acc[d] = acc[d] * corr + p * vs[j][d];
            m = mn;
        }
    }
    float inv = 1.f / l;
    float* cp = ctx + ((long)(b * SS + qi)) * DD + h * DH;
#pragma unroll
    for (int d = 0; d < DH; d += 4) {
        float4 o = {acc[d] * inv, acc[d + 1] * inv, acc[d + 2] * inv, acc[d + 3] * inv};
        *(float4*)(cp + d) = o;
    }
}

// ======================= top-k threshold + masked softmax (in place) =======================
__global__ __launch_bounds__(1024) void topk_softmax_kernel(float* __restrict__ P)
{
    const long row = (long)blockIdx.x * SS;
    __shared__ float srt[SS];
    __shared__ float r1[32], r2[32];
    const int t = threadIdx.x;

    const float val = P[row + t];
    srt[t] = val;
    __syncthreads();

    for (int k = 2; k <= SS; k <<= 1) {
        for (int j = k >> 1; j > 0; j >>= 1) {
            int ixj = t ^ j;
            if (ixj > t) {
                float a = srt[t], c = srt[ixj];
                bool up = ((t & k) == 0);
                if ((a > c) == up) { srt[t] = c; srt[ixj] = a; }
            }
            __syncthreads();
        }
    }

    const float thr = srt[SS - KSEL];
    const float mx = srt[SS - 1];

    const float efull = __expf(val - mx);
    const float ekeep = (val >= thr) ? efull : 0.f;

    float sk = ekeep, sf = efull;
#pragma unroll
    for (int o = 16; o > 0; o >>= 1) {
        sk += __shfl_xor_sync(0xffffffffu, sk, o);
        sf += __shfl_xor_sync(0xffffffffu, sf, o);
    }
    const int w = t >> 5, lane = t & 31;
    if (lane == 0) { r1[w] = sk; r2[w] = sf; }
    __syncthreads();
    if (t == 0) {
        float a = 0.f, c = 0.f;
        for (int i = 0; i < 32; i++) { a += r1[i]; c += r2[i]; }
        r1[0] = a; r2[0] = c;
    }
    __syncthreads();
    const float denom = r1[0] + 1e-9f * r2[0];
    P[row + t] = ekeep / denom;
}

// ======================= fuse + residual + LN1 =======================
__global__ __launch_bounds__(256) void fuse_ln1_kernel(
    const float* __restrict__ src, const float* __restrict__ dense,
    const float* __restrict__ sparse, const float* __restrict__ lam,
    const float* __restrict__ g, const float* __restrict__ bb,
    float* __restrict__ x)
{
    const long row = (long)blockIdx.x * DD;
    __shared__ float buf[DD];
    __shared__ float r1[8], r2[8];
    const float sig = 1.f / (1.f + __expf(-lam[0]));
    const float osig = 1.f - sig;

    float s1 = 0.f, s2 = 0.f;
    for (int d = threadIdx.x; d < DD; d += 256) {
        float v = src[row + d] + sig * dense[row + d] + osig * sparse[row + d];
        buf[d] = v; s1 += v; s2 += v * v;
    }
#pragma unroll
    for (int o = 16; o > 0; o >>= 1) {
        s1 += __shfl_xor_sync(0xffffffffu, s1, o);
        s2 += __shfl_xor_sync(0xffffffffu, s2, o);
    }
    const int w = threadIdx.x >> 5, lane = threadIdx.x & 31;
    if (lane == 0) { r1[w] = s1; r2[w] = s2; }
    __syncthreads();
    if (threadIdx.x == 0) {
        float a = 0.f, c = 0.f;
        for (int i = 0; i < 8; i++) { a += r1[i]; c += r2[i]; }
        r1[0] = a; r2[0] = c;
    }
    __syncthreads();
    const float mean = r1[0] * (1.f / DD);
    const float var = r2[0] * (1.f / DD) - mean * mean;
    const float rstd = rsqrtf(var + 1e-5f);
    for (int d = threadIdx.x; d < DD; d += 256)
        x[row + d] = (buf[d] - mean) * rstd * g[d] + bb[d];
}

// ======================= residual + LN2 -> out =======================
__global__ __launch_bounds__(256) void ln2_kernel(
    const float* __restrict__ x, const float* __restrict__ ff,
    const float* __restrict__ g, const float* __restrict__ bb,
    float* __restrict__ out)
{
    const long row = (long)blockIdx.x * DD;
    __shared__ float buf[DD];
    __shared__ float r1[8], r2[8];

    float s1 = 0.f, s2 = 0.f;
    for (int d = threadIdx.x; d < DD; d += 256) {
        float v = x[row + d] + ff[row + d];
        buf[d] = v; s1 += v; s2 += v * v;
    }
#pragma unroll
    for (int o = 16; o > 0; o >>= 1) {
        s1 += __shfl_xor_sync(0xffffffffu, s1, o);
        s2 += __shfl_xor_sync(0xffffffffu, s2, o);
    }
    const int w = threadIdx.x >> 5, lane = threadIdx.x & 31;
    if (lane == 0) { r1[w] = s1; r2[w] = s2; }
    __syncthreads();
    if (threadIdx.x == 0) {
        float a = 0.f, c = 0.f;
        for (int i = 0; i < 8; i++) { a += r1[i]; c += r2[i]; }
        r1[0] = a; r2[0] = c;
    }
    __syncthreads();
    const float mean = r1[0] * (1.f / DD);
    const float var = r2[0] * (1.f / DD) - mean * mean;
    const float rstd = rsqrtf(var + 1e-5f);
    for (int d = threadIdx.x; d < DD; d += 256)
        out[row + d] = (buf[d] - mean) * rstd * g[d] + bb[d];
}

// ======================= launch =======================
extern "C" void kernel_launch(void* const* d_in, const int* in_sizes, int n_in,
                              void* d_out, int out_size)
{
    (void)in_sizes; (void)n_in; (void)out_size;
    const float* src    = (const float*)d_in[0];
    const float* in_w   = (const float*)d_in[1];
    const float* in_b   = (const float*)d_in[2];
    const float* outp_w = (const float*)d_in[3];
    const float* outp_b = (const float*)d_in[4];
    const float* Qp_w   = (const float*)d_in[5];
    const float* Qp_b   = (const float*)d_in[6];
    const float* Kp_w   = (const float*)d_in[7];
    const float* Kp_b   = (const float*)d_in[8];
    const float* Vp_w   = (const float*)d_in[9];
    const float* Vp_b   = (const float*)d_in[10];
    const float* lam    = (const float*)d_in[11];
    const float* ff1_w  = (const float*)d_in[12];
    const float* ff1_b  = (const float*)d_in[13];
    const float* ff2_w  = (const float*)d_in[14];
    const float* ff2_b  = (const float*)d_in[15];
    const float* ln1_g  = (const float*)d_in[16];
    const float* ln1_b  = (const float*)d_in[17];
    const float* ln2_g  = (const float*)d_in[18];
    const float* ln2_b  = (const float*)d_in[19];
    float* out = (float*)d_out;

    float *qkv, *ctx, *dense, *Qlr, *Klr, *Vlr, *Vt, *P, *sparse, *x, *h1, *ff;
    cudaGetSymbolAddress((void**)&qkv,    g_qkv);
    cudaGetSymbolAddress((void**)&ctx,    g_ctx);
    cudaGetSymbolAddress((void**)&dense,  g_dense);
    cudaGetSymbolAddress((void**)&Qlr,    g_Qlr);
    cudaGetSymbolAddress((void**)&Klr,    g_Klr);
    cudaGetSymbolAddress((void**)&Vlr,    g_Vlr);
    cudaGetSymbolAddress((void**)&Vt,     g_Vt);
    cudaGetSymbolAddress((void**)&P,      g_P);
    cudaGetSymbolAddress((void**)&sparse, g_sparse);
    cudaGetSymbolAddress((void**)&x,      g_x);
    cudaGetSymbolAddress((void**)&h1,     g_h1);
    cudaGetSymbolAddress((void**)&ff,     g_ff);

    // 1. qkv = src @ in_proj_w^T + b              [4096, 3072]
    mma_gemm_nt<<<dim3(3 * DD / BN, NTOK / BM), 256>>>(
        src, in_w, in_b, qkv, 3 * DD, DD, 0, 0, 0, 1.f, 0);
    // 2. dense attention -> ctx
    attn_kernel<<<dim3(SS / 128, HH, BB), 128>>>(qkv, ctx);
    // 3. dense_output = ctx @ out_proj^T + b
    mma_gemm_nt<<<dim3(DD / BN, NTOK / BM), 256>>>(
        ctx, outp_w, outp_b, dense, DD, DD, 0, 0, 0, 1.f, 0);
    // 4-6. low-rank projections (N=64 guarded in kernel)
    mma_gemm_nt<<<dim3(1, NTOK / BM), 256>>>(
        src, Qp_w, Qp_b, Qlr, RR, DD, 0, 0, 0, 1.f, 0);
    mma_gemm_nt<<<dim3(1, NTOK / BM), 256>>>(
        src, Kp_w, Kp_b, Klr, RR, DD, 0, 0, 0, 1.f, 0);
    mma_gemm_nt<<<dim3(DD / BN, NTOK / BM), 256>>>(
        src, Vp_w, Vp_b, Vlr, DD, DD, 0, 0, 0, 1.f, 0);
    // 7. P = (Q @ K^T) / sqrt(R)  per batch       [B, 1024, 1024]
    mma_gemm_nt<<<dim3(SS / BN, SS / BM, BB), 256>>>(
        Qlr, Klr, nullptr, P, SS, RR,
        (long)SS * RR, (long)SS * RR, (long)SS * SS, 0.125f, 0);
    // 8. top-k threshold + masked softmax
    topk_softmax_kernel<<<NTOK, 1024>>>(P);
    // 9a. Vt = V^T per batch
    transpose_kernel<<<dim3(SS / 32, DD / 32, BB), 256>>>(Vlr, Vt);
    // 9b. sparse = P @ Vt^T per batch
    mma_gemm_nt<<<dim3(DD / BN, SS / BM, BB), 256>>>(
        P, Vt, nullptr, sparse, DD, SS,
        (long)SS * SS, (long)SS * DD, (long)SS * DD, 1.f, 0);
    // 10. x = LN1(src + sig*dense + (1-sig)*sparse)
    fuse_ln1_kernel<<<NTOK, 256>>>(src, dense, sparse, lam, ln1_g, ln1_b, x);
    // 11. h1 = relu(x @ ff1^T + b)                [4096, 4096]
    mma_gemm_nt<<<dim3(DFFN / BN, NTOK / BM), 256>>>(
        x, ff1_w, ff1_b, h1, DFFN, DD, 0, 0, 0, 1.f, 1);
    // 12. ff = h1 @ ff2^T + b
    mma_gemm_nt<<<dim3(DD / BN, NTOK / BM), 256>>>(
        h1, ff2_w, ff2_b, ff, DD, DFFN, 0, 0, 0, 1.f, 0);
    // 13. out = LN2(x + ff)
    ln2_kernel<<<NTOK, 256>>>(x, ff, ln2_g, ln2_b, out);
}

// round 4
// speedup vs baseline: 3.0884x; 1.3629x over previous
#include <cuda_runtime.h>
#include <cstdint>
#include <math.h>

// Problem dims
#define BB   4
#define SS   1024
#define DD   1024
#define HH   16
#define DH   64
#define RR   64
#define DFFN 4096
#define NTOK (BB*SS)       // 4096
#define KSEL 204           // int(1024*0.2)

// ---------------- scratch (device globals; no allocation allowed) ----------------
__device__ float g_qkv[(long)NTOK * 3 * DD];
__device__ float g_ctx[(long)NTOK * DD];
__device__ float g_dense[(long)NTOK * DD];
__device__ float g_Qlr[NTOK * RR];
__device__ float g_Klr[NTOK * RR];
__device__ float g_Vlr[(long)NTOK * DD];
__device__ float g_Vt[(long)NTOK * DD];
__device__ float g_P[(long)BB * SS * SS];
__device__ float g_sparse[(long)NTOK * DD];
__device__ float g_x[(long)NTOK * DD];
__device__ float g_h1[(long)NTOK * DFFN];
__device__ float g_ff[(long)NTOK * DD];

// ======================= helpers =======================
__device__ __forceinline__ uint32_t smem_u32(const void* p) {
    uint32_t a;
    asm("{ .reg .u64 t; cvta.to.shared.u64 t, %1; cvt.u32.u64 %0, t; }" : "=r"(a) : "l"(p));
    return a;
}
__device__ __forceinline__ uint32_t f2tf32(float f) {
    uint32_t u; asm("cvt.rna.tf32.f32 %0, %1;" : "=r"(u) : "f"(f)); return u;
}
__device__ __forceinline__ void cp16(uint32_t saddr, const void* g, int src_sz) {
    asm volatile("cp.async.ca.shared.global [%0], [%1], 16, %2;"
                 :: "r"(saddr), "l"(g), "r"(src_sz) : "memory");
}
#define CP_COMMIT() asm volatile("cp.async.commit_group;" ::: "memory")
#define CP_WAIT1()  asm volatile("cp.async.wait_group 1;" ::: "memory")
#define CP_WAIT0()  asm volatile("cp.async.wait_group 0;" ::: "memory")

__device__ __forceinline__ void mma_tf32(float* c, const uint32_t* a, const uint32_t* b) {
    asm volatile(
        "mma.sync.aligned.m16n8k8.row.col.f32.tf32.tf32.f32 "
        "{%0,%1,%2,%3}, {%4,%5,%6,%7}, {%8,%9}, {%0,%1,%2,%3};"
        : "+f"(c[0]), "+f"(c[1]), "+f"(c[2]), "+f"(c[3])
        : "r"(a[0]), "r"(a[1]), "r"(a[2]), "r"(a[3]), "r"(b[0]), "r"(b[1]));
}

// ======================= tf32 warp-MMA GEMM: C = alpha*A(MxK)*B^T(NxK)+bias =======================
#define BM 128
#define BN 128
#define BK 16
#define KSTR 20

__global__ __launch_bounds__(256) void mma_gemm_nt(
    const float* __restrict__ A, const float* __restrict__ B,
    const float* __restrict__ bias, float* __restrict__ C,
    int N, int K, long sA, long sB, long sC, float alpha, int relu)
{
    __shared__ float As[2][BM * KSTR];
    __shared__ float Bs[2][BN * KSTR];

    A += (long)blockIdx.z * sA;
    B += (long)blockIdx.z * sB;
    C += (long)blockIdx.z * sC;

    const int t = threadIdx.x;
    const int wid = t >> 5, l = t & 31;
    const int wm = wid >> 2, wn = wid & 3;
    const int mbase = wm * 64, nbase = wn * 32;
    const int qr = l >> 2, qc = l & 3;
    const int row0 = blockIdx.y * BM, col0 = blockIdx.x * BN;

    const uint32_t sA0 = smem_u32(&As[0][0]);
    const uint32_t sB0 = smem_u32(&Bs[0][0]);

    const int lm0 = t >> 2;
    const int lkc = (t & 3) * 4;

    float acc[4][4][4];
#pragma unroll
    for (int i = 0; i < 4; i++)
#pragma unroll
        for (int j = 0; j < 4; j++)
#pragma unroll
            for (int q = 0; q < 4; q++) acc[i][j][q] = 0.f;

    const int nc = K / BK;

    {
        const int k0 = 0;
#pragma unroll
        for (int j = 0; j < 2; j++) {
            int m = lm0 + j * 64;
            cp16(sA0 + (m * KSTR + lkc) * 4, &A[(long)(row0 + m) * K + k0 + lkc], 16);
        }
#pragma unroll
        for (int j = 0; j < 2; j++) {
            int n = lm0 + j * 64;
            bool v = (col0 + n) < N;
            const float* gp = v ? &B[(long)(col0 + n) * K + k0 + lkc] : B;
            cp16(sB0 + (n * KSTR + lkc) * 4, gp, v ? 16 : 0);
        }
        CP_COMMIT();
    }

    for (int c = 0; c < nc; c++) {
        if (c + 1 < nc) {
            const int ns = (c + 1) & 1;
            const int k0 = (c + 1) * BK;
            const uint32_t sAs = sA0 + ns * (BM * KSTR * 4);
            const uint32_t sBs = sB0 + ns * (BN * KSTR * 4);
#pragma unroll
            for (int j = 0; j < 2; j++) {
                int m = lm0 + j * 64;
                cp16(sAs + (m * KSTR + lkc) * 4, &A[(long)(row0 + m) * K + k0 + lkc], 16);
            }
#pragma unroll
            for (int j = 0; j < 2; j++) {
                int n = lm0 + j * 64;
                bool v = (col0 + n) < N;
                const float* gp = v ? &B[(long)(col0 + n) * K + k0 + lkc] : B;
                cp16(sBs + (n * KSTR + lkc) * 4, gp, v ? 16 : 0);
            }
            CP_COMMIT();
            CP_WAIT1();
        } else {
            CP_WAIT0();
        }
        __syncthreads();

        const float* as = &As[c & 1][0];
        const float* bs = &Bs[c & 1][0];
#pragma unroll
        for (int kk = 0; kk < 2; kk++) {
            const int ks = kk * 8;
            uint32_t af[4][4], bf[4][2];
#pragma unroll
            for (int mt = 0; mt < 4; mt++) {
                const int r = mbase + mt * 16 + qr;
                af[mt][0] = f2tf32(as[r * KSTR + ks + qc]);
                af[mt][1] = f2tf32(as[(r + 8) * KSTR + ks + qc]);
                af[mt][2] = f2tf32(as[r * KSTR + ks + qc + 4]);
                af[mt][3] = f2tf32(as[(r + 8) * KSTR + ks + qc + 4]);
            }
#pragma unroll
            for (int nt = 0; nt < 4; nt++) {
                const int n = nbase + nt * 8 + qr;
                bf[nt][0] = f2tf32(bs[n * KSTR + ks + qc]);
                bf[nt][1] = f2tf32(bs[n * KSTR + ks + qc + 4]);
            }
#pragma unroll
            for (int mt = 0; mt < 4; mt++)
#pragma unroll
                for (int nt = 0; nt < 4; nt++)
                    mma_tf32(acc[mt][nt], af[mt], bf[nt]);
        }
        __syncthreads();
    }

#pragma unroll
    for (int mt = 0; mt < 4; mt++) {
        const int r = row0 + mbase + mt * 16 + qr;
#pragma unroll
        for (int nt = 0; nt < 4; nt++) {
            const int cc = col0 + nbase + nt * 8 + qc * 2;
            if (cc < N) {
                float b0 = 0.f, b1 = 0.f;
                if (bias) { b0 = bias[cc]; b1 = bias[cc + 1]; }
                float v0 = acc[mt][nt][0] * alpha + b0;
                float v1 = acc[mt][nt][1] * alpha + b1;
                float v2 = acc[mt][nt][2] * alpha + b0;
                float v3 = acc[mt][nt][3] * alpha + b1;
                if (relu) {
                    v0 = fmaxf(v0, 0.f); v1 = fmaxf(v1, 0.f);
                    v2 = fmaxf(v2, 0.f); v3 = fmaxf(v3, 0.f);
                }
                float2 p0 = {v0, v1}, p1 = {v2, v3};
                *(float2*)&C[(long)r * N + cc] = p0;
                *(float2*)&C[(long)(r + 8) * N + cc] = p1;
            }
        }
    }
}

// ======================= transpose: Vt[b][d][s] = V[b][s][d] =======================
__global__ __launch_bounds__(256) void transpose_kernel(const float* __restrict__ V,
                                                        float* __restrict__ Vt)
{
    __shared__ float tile[32][33];
    const float* Vb = V + (long)blockIdx.z * SS * DD;
    float* Vtb = Vt + (long)blockIdx.z * SS * DD;
    const int s0 = blockIdx.x * 32, d0 = blockIdx.y * 32;
    const int tx = threadIdx.x & 31, ty0 = threadIdx.x >> 5;
#pragma unroll
    for (int i = 0; i < 4; i++) {
        int ty = ty0 + i * 8;
        tile[ty][tx] = Vb[(long)(s0 + ty) * DD + d0 + tx];
    }
    __syncthreads();
#pragma unroll
    for (int i = 0; i < 4; i++) {
        int ty = ty0 + i * 8;
        Vtb[(long)(d0 + ty) * SS + s0 + tx] = tile[tx][ty];
    }
}

// ======================= dense MHA: tf32 tensor-core flash attention =======================
// grid (SS/128, HH, BB), block 256 (8 warps, 16 q-rows per warp), key tile 64.
#define FA_STR 68
#define FA_SMEM ((128 * FA_STR + 64 * FA_STR + 64 * FA_STR) * 4)

__global__ __launch_bounds__(256) void flash_attn_kernel(const float* __restrict__ qkv,
                                                         float* __restrict__ ctx)
{
    extern __shared__ float fsm[];
    float* ps = fsm;                      // 128 x FA_STR  (Q staging, then P)
    float* ks = fsm + 128 * FA_STR;       // 64 x FA_STR   (K tile  [key][dh])
    float* vs = ks + 64 * FA_STR;         // 64 x FA_STR   (V tile transposed [dh][key])

    const int t = threadIdx.x, w = t >> 5, l = t & 31;
    const int qr = l >> 2, qc = l & 3;
    const int q0 = blockIdx.x * 128, h = blockIdx.y, b = blockIdx.z;
    const int wr = w * 16;

    const float* Qg = qkv + (long)(b * SS + q0) * (3 * DD) + h * DH;
    const float* Kg = qkv + (long)(b * SS) * (3 * DD) + DD + h * DH;
    const float* Vg = qkv + (long)(b * SS) * (3 * DD) + 2 * DD + h * DH;

    // ---- stage Q into ps (coalesced), then load fragments ----
#pragma unroll
    for (int i = 0; i < 8; i++) {
        int idx = t + i * 256;                 // 0..2047
        int r = idx >> 4, c4 = (idx & 15) << 2;
        float4 v = *(const float4*)(Qg + (long)r * (3 * DD) + c4);
        *(float4*)&ps[r * FA_STR + c4] = v;
    }
    __syncthreads();
    uint32_t qa[8][4];
#pragma unroll
    for (int k = 0; k < 8; k++) {
        qa[k][0] = f2tf32(ps[(wr + qr) * FA_STR + k * 8 + qc]);
        qa[k][1] = f2tf32(ps[(wr + qr + 8) * FA_STR + k * 8 + qc]);
        qa[k][2] = f2tf32(ps[(wr + qr) * FA_STR + k * 8 + qc + 4]);
        qa[k][3] = f2tf32(ps[(wr + qr + 8) * FA_STR + k * 8 + qc + 4]);
    }
    __syncthreads();   // ps free

    float m0 = -1e30f, m1 = -1e30f, l0 = 0.f, l1 = 0.f;
    float o[8][4];
#pragma unroll
    for (int n = 0; n < 8; n++)
#pragma unroll
        for (int i = 0; i < 4; i++) o[n][i] = 0.f;

    for (int kt = 0; kt < SS; kt += 64) {
        // ---- load K tile (row-major) and V tile (transposed) ----
#pragma unroll
        for (int i = 0; i < 4; i++) {
            int idx = t + i * 256;             // 0..1023
            int r = idx >> 4, c4 = (idx & 15) << 2;
            float4 kv = *(const float4*)(Kg + (long)(kt + r) * (3 * DD) + c4);
            *(float4*)&ks[r * FA_STR + c4] = kv;
            float4 vv = *(const float4*)(Vg + (long)(kt + r) * (3 * DD) + c4);
            vs[(c4 + 0) * FA_STR + r] = vv.x;
            vs[(c4 + 1) * FA_STR + r] = vv.y;
            vs[(c4 + 2) * FA_STR + r] = vv.z;
            vs[(c4 + 3) * FA_STR + r] = vv.w;
        }
        __syncthreads();

        // ---- S = Q @ K^T (warp rows wr..wr+15, keys 0..63 of tile) ----
        float sa[8][4];
#pragma unroll
        for (int n = 0; n < 8; n++)
#pragma unroll
            for (int i = 0; i < 4; i++) sa[n][i] = 0.f;
#pragma unroll
        for (int k = 0; k < 8; k++) {
#pragma unroll
            for (int n = 0; n < 8; n++) {
                uint32_t bf[2];
                bf[0] = f2tf32(ks[(n * 8 + qr) * FA_STR + k * 8 + qc]);
                bf[1] = f2tf32(ks[(n * 8 + qr) * FA_STR + k * 8 + qc + 4]);
                mma_tf32(sa[n], qa[k], bf);
            }
        }

        // ---- online softmax ----
        float rm0 = -1e30f, rm1 = -1e30f;
#pragma unroll
        for (int n = 0; n < 8; n++) {
            sa[n][0] *= 0.125f; sa[n][1] *= 0.125f;
            sa[n][2] *= 0.125f; sa[n][3] *= 0.125f;
            rm0 = fmaxf(rm0, fmaxf(sa[n][0], sa[n][1]));
            rm1 = fmaxf(rm1, fmaxf(sa[n][2], sa[n][3]));
        }
        rm0 = fmaxf(rm0, __shfl_xor_sync(0xffffffffu, rm0, 1));
        rm0 = fmaxf(rm0, __shfl_xor_sync(0xffffffffu, rm0, 2));
        rm1 = fmaxf(rm1, __shfl_xor_sync(0xffffffffu, rm1, 1));
        rm1 = fmaxf(rm1, __shfl_xor_sync(0xffffffffu, rm1, 2));

        const float nm0 = fmaxf(m0, rm0), nm1 = fmaxf(m1, rm1);
        const float c0 = __expf(m0 - nm0), c1 = __expf(m1 - nm1);
        float rs0 = 0.f, rs1 = 0.f;
#pragma unroll
        for (int n = 0; n < 8; n++) {
            float p0 = __expf(sa[n][0] - nm0);
            float p1 = __expf(sa[n][1] - nm0);
            float p2 = __expf(sa[n][2] - nm1);
            float p3 = __expf(sa[n][3] - nm1);
            rs0 += p0 + p1; rs1 += p2 + p3;
            float2 w0 = {p0, p1}, w1 = {p2, p3};
            *(float2*)&ps[(wr + qr) * FA_STR + n * 8 + 2 * qc] = w0;
            *(float2*)&ps[(wr + qr + 8) * FA_STR + n * 8 + 2 * qc] = w1;
            o[n][0] *= c0; o[n][1] *= c0; o[n][2] *= c1; o[n][3] *= c1;
        }
        rs0 += __shfl_xor_sync(0xffffffffu, rs0, 1);
        rs0 += __shfl_xor_sync(0xffffffffu, rs0, 2);
        rs1 += __shfl_xor_sync(0xffffffffu, rs1, 1);
        rs1 += __shfl_xor_sync(0xffffffffu, rs1, 2);
        l0 = l0 * c0 + rs0; l1 = l1 * c1 + rs1;
        m0 = nm0; m1 = nm1;

        __syncwarp();   // P rows for this warp written by all its lanes

        // ---- O += P @ V ----
#pragma unroll
        for (int k = 0; k < 8; k++) {
            uint32_t pa[4];
            pa[0] = f2tf32(ps[(wr + qr) * FA_STR + k * 8 + qc]);
            pa[1] = f2tf32(ps[(wr + qr + 8) * FA_STR + k * 8 + qc]);
            pa[2] = f2tf32(ps[(wr + qr) * FA_STR + k * 8 + qc + 4]);
            pa[3] = f2tf32(ps[(wr + qr + 8) * FA_STR + k * 8 + qc + 4]);
#pragma unroll
            for (int n = 0; n < 8; n++) {
                uint32_t bf[2];
                bf[0] = f2tf32(vs[(n * 8 + qr) * FA_STR + k * 8 + qc]);
                bf[1] = f2tf32(vs[(n * 8 + qr) * FA_STR + k * 8 + qc + 4]);
                mma_tf32(o[n], pa, bf);
            }
        }
        __syncthreads();   // before ks/vs overwritten next tile
    }

    // ---- epilogue ----
    const float i0 = 1.f / l0, i1 = 1.f / l1;
    float* Og = ctx + (long)(b * SS + q0 + wr) * DD + h * DH;
#pragma unroll
    for (int n = 0; n < 8; n++) {
        float2 w0 = {o[n][0] * i0, o[n][1] * i0};
        float2 w1 = {o[n][2] * i1, o[n][3] * i1};
        *(float2*)&Og[(long)qr * DD + n * 8 + 2 * qc] = w0;
        *(float2*)&Og[(long)(qr + 8) * DD + n * 8 + 2 * qc] = w1;
    }
}

// ======================= radix-select top-k + masked softmax (in place) =======================
__global__ __launch_bounds__(256) void topk_softmax_kernel(float* __restrict__ P)
{
    const long base = (long)blockIdx.x * SS;
    __shared__ float vals[SS];
    __shared__ unsigned keys[SS];
    __shared__ unsigned hist[256];
    __shared__ float redA[8], redB[8];
    __shared__ unsigned s_prefix;
    __shared__ int s_need;

    const int t = threadIdx.x;
    const int w = t >> 5, lane = t & 31;

    float lmax = -1e30f;
#pragma unroll
    for (int i = 0; i < 4; i++) {
        float v = P[base + t + i * 256];
        vals[t + i * 256] = v;
        unsigned u = __float_as_uint(v);
        u ^= (u >> 31) ? 0xFFFFFFFFu : 0x80000000u;
        keys[t + i * 256] = u;
        lmax = fmaxf(lmax, v);
    }
#pragma unroll
    for (int o = 16; o > 0; o >>= 1)
        lmax = fmaxf(lmax, __shfl_xor_sync(0xffffffffu, lmax, o));
    if (lane == 0) redA[w] = lmax;
    __syncthreads();
    float mx = redA[0];
#pragma unroll
    for (int i = 1; i < 8; i++) mx = fmaxf(mx, redA[i]);

    unsigned prefix = 0;
    int need = KSEL;
#pragma unroll
    for (int pass = 0; pass < 4; pass++) {
        const int shift = 24 - 8 * pass;
        const unsigned hmask = pass ? (0xFFFFFFFFu << (shift + 8)) : 0u;
        hist[t] = 0;
        if (t < 256 - 0) {}   // all 256 threads zero one bin each
        __syncthreads();
#pragma unroll
        for (int i = 0; i < 4; i++) {
            unsigned u = keys[t + i * 256];
            if ((u & hmask) == prefix)
                atomicAdd(&hist[(u >> shift) & 0xFFu], 1u);
        }
        __syncthreads();
        if (t == 0) {
            int cum = 0, bsel = 0;
            for (int bbin = 255; bbin >= 0; bbin--) {
                int hh = (int)hist[bbin];
                if (cum + hh >= need) { bsel = bbin; break; }
                cum += hh;
            }
            s_prefix = prefix | ((unsigned)bsel << shift);
            s_need = need - cum;
        }
        __syncthreads();
        prefix = s_prefix;
        need = s_need;
        __syncthreads();
    }
    const unsigned thr = prefix;

    float e[4];
    float sk = 0.f, sf = 0.f;
#pragma unroll
    for (int i = 0; i < 4; i++) {
        float v = vals[t + i * 256];
        float ef = __expf(v - mx);
        bool kp = keys[t + i * 256] >= thr;
        e[i] = kp ? ef : 0.f;
        sk += e[i];
        sf += ef;
    }
#pragma unroll
    for (int o = 16; o > 0; o >>= 1) {
        sk += __shfl_xor_sync(0xffffffffu, sk, o);
        sf += __shfl_xor_sync(0xffffffffu, sf, o);
    }
    if (lane == 0) { redA[w] = sk; redB[w] = sf; }
    __syncthreads();
    float tk = 0.f, tf = 0.f;
#pragma unroll
    for (int i = 0; i < 8; i++) { tk += redA[i]; tf += redB[i]; }
    const float denom = tk + 1e-9f * tf;
#pragma unroll
    for (int i = 0; i < 4; i++)
        P[base + t + i * 256] = e[i] / denom;
}

// ======================= fuse + residual + LN1 =======================
__global__ __launch_bounds__(256) void fuse_ln1_kernel(
    const float* __restrict__ src, const float* __restrict__ dense,
    const float* __restrict__ sparse, const float* __restrict__ lam,
    const float* __restrict__ g, const float* __restrict__ bb,
    float* __restrict__ x)
{
    const long row = (long)blockIdx.x * DD;
    __shared__ float buf[DD];
    __shared__ float r1[8], r2[8];
    const float sig = 1.f / (1.f + __expf(-lam[0]));
    const float osig = 1.f - sig;

    float s1 = 0.f, s2 = 0.f;
    for (int d = threadIdx.x; d < DD; d += 256) {
        float v = src[row + d] + sig * dense[row + d] + osig * sparse[row + d];
        buf[d] = v; s1 += v; s2 += v * v;
    }
#pragma unroll
    for (int o = 16; o > 0; o >>= 1) {
        s1 += __shfl_xor_sync(0xffffffffu, s1, o);
        s2 += __shfl_xor_sync(0xffffffffu, s2, o);
    }
    const int w = threadIdx.x >> 5, lane = threadIdx.x & 31;
    if (lane == 0) { r1[w] = s1; r2[w] = s2; }
    __syncthreads();
    if (threadIdx.x == 0) {
        float a = 0.f, c = 0.f;
        for (int i = 0; i < 8; i++) { a += r1[i]; c += r2[i]; }
        r1[0] = a; r2[0] = c;
    }
    __syncthreads();
    const float mean = r1[0] * (1.f / DD);
    const float var = r2[0] * (1.f / DD) - mean * mean;
    const float rstd = rsqrtf(var + 1e-5f);
    for (int d = threadIdx.x; d < DD; d += 256)
        x[row + d] = (buf[d] - mean) * rstd * g[d] + bb[d];
}

// ======================= residual + LN2 -> out =======================
__global__ __launch_bounds__(256) void ln2_kernel(
    const float* __restrict__ x, const float* __restrict__ ff,
    const float* __restrict__ g, const float* __restrict__ bb,
    float* __restrict__ out)
{
    const long row = (long)blockIdx.x * DD;
    __shared__ float buf[DD];
    __shared__ float r1[8], r2[8];

    float s1 = 0.f, s2 = 0.f;
    for (int d = threadIdx.x; d < DD; d += 256) {
        float v = x[row + d] + ff[row + d];
        buf[d] = v; s1 += v; s2 += v * v;
    }
#pragma unroll
    for (int o = 16; o > 0; o >>= 1) {
        s1 += __shfl_xor_sync(0xffffffffu, s1, o);
        s2 += __shfl_xor_sync(0xffffffffu, s2, o);
    }
    const int w = threadIdx.x >> 5, lane = threadIdx.x & 31;
    if (lane == 0) { r1[w] = s1; r2[w] = s2; }
    __syncthreads();
    if (threadIdx.x == 0) {
        float a = 0.f, c = 0.f;
        for (int i = 0; i < 8; i++) { a += r1[i]; c += r2[i]; }
        r1[0] = a; r2[0] = c;
    }
    __syncthreads();
    const float mean = r1[0] * (1.f / DD);
    const float var = r2[0] * (1.f / DD) - mean * mean;
    const float rstd = rsqrtf(var + 1e-5f);
    for (int d = threadIdx.x; d < DD; d += 256)
        out[row + d] = (buf[d] - mean) * rstd * g[d] + bb[d];
}

// ======================= launch =======================
extern "C" void kernel_launch(void* const* d_in, const int* in_sizes, int n_in,
                              void* d_out, int out_size)
{
    (void)in_sizes; (void)n_in; (void)out_size;
    const float* src    = (const float*)d_in[0];
    const float* in_w   = (const float*)d_in[1];
    const float* in_b   = (const float*)d_in[2];
    const float* outp_w = (const float*)d_in[3];
    const float* outp_b = (const float*)d_in[4];
    const float* Qp_w   = (const float*)d_in[5];
    const float* Qp_b   = (const float*)d_in[6];
    const float* Kp_w   = (const float*)d_in[7];
    const float* Kp_b   = (const float*)d_in[8];
    const float* Vp_w   = (const float*)d_in[9];
    const float* Vp_b   = (const float*)d_in[10];
    const float* lam    = (const float*)d_in[11];
    const float* ff1_w  = (const float*)d_in[12];
    const float* ff1_b  = (const float*)d_in[13];
    const float* ff2_w  = (const float*)d_in[14];
    const float* ff2_b  = (const float*)d_in[15];
    const float* ln1_g  = (const float*)d_in[16];
    const float* ln1_b  = (const float*)d_in[17];
    const float* ln2_g  = (const float*)d_in[18];
    const float* ln2_b  = (const float*)d_in[19];
    float* out = (float*)d_out;

    float *qkv, *ctx, *dense, *Qlr, *Klr, *Vlr, *Vt, *P, *sparse, *x, *h1, *ff;
    cudaGetSymbolAddress((void**)&qkv,    g_qkv);
    cudaGetSymbolAddress((void**)&ctx,    g_ctx);
    cudaGetSymbolAddress((void**)&dense,  g_dense);
    cudaGetSymbolAddress((void**)&Qlr,    g_Qlr);
    cudaGetSymbolAddress((void**)&Klr,    g_Klr);
    cudaGetSymbolAddress((void**)&Vlr,    g_Vlr);
    cudaGetSymbolAddress((void**)&Vt,     g_Vt);
    cudaGetSymbolAddress((void**)&P,      g_P);
    cudaGetSymbolAddress((void**)&sparse, g_sparse);
    cudaGetSymbolAddress((void**)&x,      g_x);
    cudaGetSymbolAddress((void**)&h1,     g_h1);
    cudaGetSymbolAddress((void**)&ff,     g_ff);

    cudaFuncSetAttribute(flash_attn_kernel, cudaFuncAttributeMaxDynamicSharedMemorySize, FA_SMEM);

    // 1. qkv = src @ in_proj_w^T + b              [4096, 3072]
    mma_gemm_nt<<<dim3(3 * DD / BN, NTOK / BM), 256>>>(
        src, in_w, in_b, qkv, 3 * DD, DD, 0, 0, 0, 1.f, 0);
    // 2. dense attention -> ctx (tensor-core flash attention)
    flash_attn_kernel<<<dim3(SS / 128, HH, BB), 256, FA_SMEM>>>(qkv, ctx);
    // 3. dense_output = ctx @ out_proj^T + b
    mma_gemm_nt<<<dim3(DD / BN, NTOK / BM), 256>>>(
        ctx, outp_w, outp_b, dense, DD, DD, 0, 0, 0, 1.f, 0);
    // 4-6. low-rank projections
    mma_gemm_nt<<<dim3(1, NTOK / BM), 256>>>(
        src, Qp_w, Qp_b, Qlr, RR, DD, 0, 0, 0, 1.f, 0);
    mma_gemm_nt<<<dim3(1, NTOK / BM), 256>>>(
        src, Kp_w, Kp_b, Klr, RR, DD, 0, 0, 0, 1.f, 0);
    mma_gemm_nt<<<dim3(DD / BN, NTOK / BM), 256>>>(
        src, Vp_w, Vp_b, Vlr, DD, DD, 0, 0, 0, 1.f, 0);
    // 7. P = (Q @ K^T) / sqrt(R)  per batch       [B, 1024, 1024]
    mma_gemm_nt<<<dim3(SS / BN, SS / BM, BB), 256>>>(
        Qlr, Klr, nullptr, P, SS, RR,
        (long)SS * RR, (long)SS * RR, (long)SS * SS, 0.125f, 0);
    // 8. radix top-k + masked softmax
    topk_softmax_kernel<<<NTOK, 256>>>(P);
    // 9a. Vt = V^T per batch
    transpose_kernel<<<dim3(SS / 32, DD / 32, BB), 256>>>(Vlr, Vt);
    // 9b. sparse = P @ Vt^T per batch
    mma_gemm_nt<<<dim3(DD / BN, SS / BM, BB), 256>>>(
        P, Vt, nullptr, sparse, DD, SS,
        (long)SS * SS, (long)SS * DD, (long)SS * DD, 1.f, 0);
    // 10. x = LN1(src + sig*dense + (1-sig)*sparse)
    fuse_ln1_kernel<<<NTOK, 256>>>(src, dense, sparse, lam, ln1_g, ln1_b, x);
    // 11. h1 = relu(x @ ff1^T + b)                [4096, 4096]
    mma_gemm_nt<<<dim3(DFFN / BN, NTOK / BM), 256>>>(
        x, ff1_w, ff1_b, h1, DFFN, DD, 0, 0, 0, 1.f, 1);
    // 12. ff = h1 @ ff2^T + b
    mma_gemm_nt<<<dim3(DD / BN, NTOK / BM), 256>>>(
        h1, ff2_w, ff2_b, ff, DD, DFFN, 0, 0, 0, 1.f, 0);
    // 13. out = LN2(x + ff)
    ln2_kernel<<<NTOK, 256>>>(x, ff, ln2_g, ln2_b, out);
}

// round 5
// speedup vs baseline: 5.2936x; 1.7140x over previous
#include <cuda_runtime.h>
#include <cuda_fp16.h>
#include <cstdint>
#include <math.h>

// Problem dims
#define BB   4
#define SS   1024
#define DD   1024
#define HH   16
#define DH   64
#define RR   64
#define DFFN 4096
#define NTOK (BB*SS)       // 4096
#define KSEL 204           // int(1024*0.2)

// ---------------- scratch (device globals; no allocation allowed) ----------------
// half weight copies
__device__ __half g_hw_in[(long)3 * DD * DD];
__device__ __half g_hw_out[(long)DD * DD];
__device__ __half g_hw_Qp[RR * DD];
__device__ __half g_hw_Kp[RR * DD];
__device__ __half g_hw_Vp[(long)DD * DD];
__device__ __half g_hw_f1[(long)DFFN * DD];
__device__ __half g_hw_f2[(long)DD * DFFN];
// half activations
__device__ __half g_src_h[(long)NTOK * DD];
__device__ __half g_qkv_h[(long)NTOK * 3 * DD];
__device__ __half g_ctx_h[(long)NTOK * DD];
__device__ __half g_Qlr_h[NTOK * RR];
__device__ __half g_Klr_h[NTOK * RR];
__device__ __half g_Vlr_h[(long)NTOK * DD];
__device__ __half g_Vt_h[(long)NTOK * DD];
__device__ __half g_Ph[(long)BB * SS * SS];
__device__ __half g_x_h[(long)NTOK * DD];
__device__ __half g_h1_h[(long)NTOK * DFFN];
// f32 buffers
__device__ float g_P[(long)BB * SS * SS];     // raw scores
__device__ float g_dense[(long)NTOK * DD];
__device__ float g_sparse[(long)NTOK * DD];
__device__ float g_x[(long)NTOK * DD];
__device__ float g_ff[(long)NTOK * DD];

// ======================= helpers =======================
__device__ __forceinline__ uint32_t smem_u32(const void* p) {
    uint32_t a;
    asm("{ .reg .u64 t; cvta.to.shared.u64 t, %1; cvt.u32.u64 %0, t; }" : "=r"(a) : "l"(p));
    return a;
}
__device__ __forceinline__ void cp16(uint32_t saddr, const void* g, int src_sz) {
    asm volatile("cp.async.ca.shared.global [%0], [%1], 16, %2;"
                 :: "r"(saddr), "l"(g), "r"(src_sz) : "memory");
}
#define CP_COMMIT() asm volatile("cp.async.commit_group;" ::: "memory")
#define CP_WAIT1()  asm volatile("cp.async.wait_group 1;" ::: "memory")
#define CP_WAIT0()  asm volatile("cp.async.wait_group 0;" ::: "memory")

__device__ __forceinline__ void mma_f16(float* c, const uint32_t* a, const uint32_t* b) {
    asm volatile(
        "mma.sync.aligned.m16n8k16.row.col.f32.f16.f16.f32 "
        "{%0,%1,%2,%3}, {%4,%5,%6,%7}, {%8,%9}, {%0,%1,%2,%3};"
        : "+f"(c[0]), "+f"(c[1]), "+f"(c[2]), "+f"(c[3])
        : "r"(a[0]), "r"(a[1]), "r"(a[2]), "r"(a[3]), "r"(b[0]), "r"(b[1]));
}
__device__ __forceinline__ uint32_t h2u(float x, float y) {
    __half2 h = __floats2half2_rn(x, y);
    return *(uint32_t*)&h;
}

// ======================= f32 -> f16 converter =======================
__global__ __launch_bounds__(256) void f2h_kernel(const float* __restrict__ in,
                                                  __half* __restrict__ out, int n)
{
    int i = (blockIdx.x * 256 + threadIdx.x) * 4;
    if (i < n) {
        float4 v = *(const float4*)(in + i);
        __half2 a = __floats2half2_rn(v.x, v.y);
        __half2 b = __floats2half2_rn(v.z, v.w);
        *(__half2*)(out + i) = a;
        *(__half2*)(out + i + 2) = b;
    }
}

// ======================= fp16 warp-MMA GEMM: C = alpha*A(MxK)*B^T(NxK)+bias =======================
// CTA tile 128x128x32(halves), 8 warps (2x4), warp tile 64x32, double-buffered cp.async.
#define BM 128
#define BN 128
#define BKH 32     // halves per K chunk (= 16 b32)
#define KSTRH 20   // b32 row stride (16 data + 4 pad): 16B-aligned, conflict-free frags

__global__ __launch_bounds__(256) void hgemm_nt(
    const __half* __restrict__ A, const __half* __restrict__ B,
    const float* __restrict__ bias, void* __restrict__ Cout,
    int N, int K, long sA, long sB, long sC, float alpha, int relu, int out_half)
{
    __shared__ uint32_t As[2][BM * KSTRH];
    __shared__ uint32_t Bs[2][BM * KSTRH];

    A += (long)blockIdx.z * sA;
    B += (long)blockIdx.z * sB;

    const int t = threadIdx.x;
    const int wid = t >> 5, l = t & 31;
    const int wm = wid >> 2, wn = wid & 3;
    const int mbase = wm * 64, nbase = wn * 32;
    const int qr = l >> 2, qc = l & 3;
    const int row0 = blockIdx.y * BM, col0 = blockIdx.x * BN;

    const uint32_t sA0 = smem_u32(&As[0][0]);
    const uint32_t sB0 = smem_u32(&Bs[0][0]);

    const int lr = t >> 2;            // 0..63
    const int lc4 = (t & 3) * 4;      // b32 col 0,4,8,12 ; halves offset = lc4*2

    float acc[4][4][4];
#pragma unroll
    for (int i = 0; i < 4; i++)
#pragma unroll
        for (int j = 0; j < 4; j++)
#pragma unroll
            for (int q = 0; q < 4; q++) acc[i][j][q] = 0.f;

    const int nc = K / BKH;

    // ---- prefetch stage 0 ----
    {
#pragma unroll
        for (int j = 0; j < 2; j++) {
            int m = lr + j * 64;
            cp16(sA0 + (m * KSTRH + lc4) * 4, &A[(long)(row0 + m) * K + lc4 * 2], 16);
        }
#pragma unroll
        for (int j = 0; j < 2; j++) {
            int n = lr + j * 64;
            bool v = (col0 + n) < N;
            const __half* gp = v ? &B[(long)(col0 + n) * K + lc4 * 2] : B;
            cp16(sB0 + (n * KSTRH + lc4) * 4, gp, v ? 16 : 0);
        }
        CP_COMMIT();
    }

    for (int c = 0; c < nc; c++) {
        if (c + 1 < nc) {
            const int ns = (c + 1) & 1;
            const int k0 = (c + 1) * BKH;
            const uint32_t sAs = sA0 + ns * (BM * KSTRH * 4);
            const uint32_t sBs = sB0 + ns * (BM * KSTRH * 4);
#pragma unroll
            for (int j = 0; j < 2; j++) {
                int m = lr + j * 64;
                cp16(sAs + (m * KSTRH + lc4) * 4, &A[(long)(row0 + m) * K + k0 + lc4 * 2], 16);
            }
#pragma unroll
            for (int j = 0; j < 2; j++) {
                int n = lr + j * 64;
                bool v = (col0 + n) < N;
                const __half* gp = v ? &B[(long)(col0 + n) * K + k0 + lc4 * 2] : B;
                cp16(sBs + (n * KSTRH + lc4) * 4, gp, v ? 16 : 0);
            }
            CP_COMMIT();
            CP_WAIT1();
        } else {
            CP_WAIT0();
        }
        __syncthreads();

        const uint32_t* as = &As[c & 1][0];
        const uint32_t* bs = &Bs[c & 1][0];
#pragma unroll
        for (int kk = 0; kk < 2; kk++) {
            const int k8 = kk * 8;
            uint32_t af[4][4], bf[4][2];
#pragma unroll
            for (int mt = 0; mt < 4; mt++) {
                const int r = mbase + mt * 16 + qr;
                af[mt][0] = as[r * KSTRH + k8 + qc];
                af[mt][1] = as[(r + 8) * KSTRH + k8 + qc];
                af[mt][2] = as[r * KSTRH + k8 + qc + 4];
                af[mt][3] = as[(r + 8) * KSTRH + k8 + qc + 4];
            }
#pragma unroll
            for (int nt = 0; nt < 4; nt++) {
                const int n = nbase + nt * 8 + qr;
                bf[nt][0] = bs[n * KSTRH + k8 + qc];
                bf[nt][1] = bs[n * KSTRH + k8 + qc + 4];
            }
#pragma unroll
            for (int mt = 0; mt < 4; mt++)
#pragma unroll
                for (int nt = 0; nt < 4; nt++)
                    mma_f16(acc[mt][nt], af[mt], bf[nt]);
        }
        __syncthreads();
    }

    // ---- epilogue ----
#pragma unroll
    for (int mt = 0; mt < 4; mt++) {
        const int r = row0 + mbase + mt * 16 + qr;
#pragma unroll
        for (int nt = 0; nt < 4; nt++) {
            const int cc = col0 + nbase + nt * 8 + qc * 2;
            if (cc < N) {
                float b0 = 0.f, b1 = 0.f;
                if (bias) { b0 = bias[cc]; b1 = bias[cc + 1]; }
                float v0 = acc[mt][nt][0] * alpha + b0;
                float v1 = acc[mt][nt][1] * alpha + b1;
                float v2 = acc[mt][nt][2] * alpha + b0;
                float v3 = acc[mt][nt][3] * alpha + b1;
                if (relu) {
                    v0 = fmaxf(v0, 0.f); v1 = fmaxf(v1, 0.f);
                    v2 = fmaxf(v2, 0.f); v3 = fmaxf(v3, 0.f);
                }
                if (out_half) {
                    __half* C = (__half*)Cout + blockIdx.z * sC;
                    *(__half2*)&C[(long)r * N + cc] = __floats2half2_rn(v0, v1);
                    *(__half2*)&C[(long)(r + 8) * N + cc] = __floats2half2_rn(v2, v3);
                } else {
                    float* C = (float*)Cout + blockIdx.z * sC;
                    float2 p0 = {v0, v1}, p1 = {v2, v3};
                    *(float2*)&C[(long)r * N + cc] = p0;
                    *(float2*)&C[(long)(r + 8) * N + cc] = p1;
                }
            }
        }
    }
}

// ======================= half transpose: Vt[b][d][s] = V[b][s][d] =======================
__global__ __launch_bounds__(256) void transpose_h_kernel(const __half* __restrict__ V,
                                                          __half* __restrict__ Vt)
{
    __shared__ __half tile[32][33];
    const __half* Vb = V + (long)blockIdx.z * SS * DD;
    __half* Vtb = Vt + (long)blockIdx.z * SS * DD;
    const int s0 = blockIdx.x * 32, d0 = blockIdx.y * 32;
    const int tx = threadIdx.x & 31, ty0 = threadIdx.x >> 5;
#pragma unroll
    for (int i = 0; i < 4; i++) {
        int ty = ty0 + i * 8;
        tile[ty][tx] = Vb[(long)(s0 + ty) * DD + d0 + tx];
    }
    __syncthreads();
#pragma unroll
    for (int i = 0; i < 4; i++) {
        int ty = ty0 + i * 8;
        Vtb[(long)(d0 + ty) * SS + s0 + tx] = tile[tx][ty];
    }
}

// ======================= dense MHA: fp16 tensor-core flash attention =======================
// grid (SS/128, HH, BB), block 256 (8 warps x 16 q-rows), key tile 64, fp32 accum/softmax.
#define FSTR 36   // b32 row stride (32 data + 4 pad)

__global__ __launch_bounds__(256) void flash_attn_kernel(const __half* __restrict__ qkv,
                                                         __half* __restrict__ ctx)
{
    __shared__ uint32_t ps[128 * FSTR];   // Q staging then P (half2)
    __shared__ uint32_t ks[64 * FSTR];    // K tile [key][dh]
    __shared__ uint32_t vs[64 * FSTR];    // V tile transposed [dh][key]
    __half* vs_h = (__half*)vs;

    const int t = threadIdx.x, w = t >> 5, l = t & 31;
    const int qr = l >> 2, qc = l & 3;
    const int q0 = blockIdx.x * 128, h = blockIdx.y, b = blockIdx.z;
    const int wr = w * 16;

    const __half* Qg = qkv + (long)(b * SS + q0) * (3 * DD) + h * DH;
    const __half* Kg = qkv + (long)(b * SS) * (3 * DD) + DD + h * DH;
    const __half* Vg = qkv + (long)(b * SS) * (3 * DD) + 2 * DD + h * DH;

    // ---- stage Q (128 rows x 32 b32), then fragments ----
#pragma unroll
    for (int i = 0; i < 4; i++) {
        int idx = t + i * 256;                  // 0..1023
        int r = idx >> 3, c16 = idx & 7;
        float4 v = *(const float4*)(Qg + (long)r * (3 * DD) + c16 * 8);
        *(float4*)&ps[r * FSTR + c16 * 4] = v;
    }
    __syncthreads();
    uint32_t qa[4][4];
#pragma unroll
    for (int k = 0; k < 4; k++) {
        qa[k][0] = ps[(wr + qr) * FSTR + k * 8 + qc];
        qa[k][1] = ps[(wr + qr + 8) * FSTR + k * 8 + qc];
        qa[k][2] = ps[(wr + qr) * FSTR + k * 8 + qc + 4];
        qa[k][3] = ps[(wr + qr + 8) * FSTR + k * 8 + qc + 4];
    }
    __syncthreads();

    float m0 = -1e30f, m1 = -1e30f, l0 = 0.f, l1 = 0.f;
    float o[8][4];
#pragma unroll
    for (int n = 0; n < 8; n++)
#pragma unroll
        for (int i = 0; i < 4; i++) o[n][i] = 0.f;

    for (int kt = 0; kt < SS; kt += 64) {
        // ---- K tile + transposed V tile ----
#pragma unroll
        for (int i = 0; i < 2; i++) {
            int idx = t + i * 256;              // 0..511
            int r = idx >> 3, c16 = idx & 7;
            float4 kv = *(const float4*)(Kg + (long)(kt + r) * (3 * DD) + c16 * 8);
            *(float4*)&ks[r * FSTR + c16 * 4] = kv;
            float4 vv = *(const float4*)(Vg + (long)(kt + r) * (3 * DD) + c16 * 8);
            const __half* vh = (const __half*)&vv;
#pragma unroll
            for (int j = 0; j < 8; j++)
                vs_h[(c16 * 8 + j) * (2 * FSTR) + r] = vh[j];
        }
        __syncthreads();

        // ---- S = Q @ K^T ----
        float sa[8][4];
#pragma unroll
        for (int n = 0; n < 8; n++)
#pragma unroll
            for (int i = 0; i < 4; i++) sa[n][i] = 0.f;
#pragma unroll
        for (int k = 0; k < 4; k++) {
#pragma unroll
            for (int n = 0; n < 8; n++) {
                uint32_t bf[2];
                bf[0] = ks[(n * 8 + qr) * FSTR + k * 8 + qc];
                bf[1] = ks[(n * 8 + qr) * FSTR + k * 8 + qc + 4];
                mma_f16(sa[n], qa[k], bf);
            }
        }

        // ---- online softmax (fp32) ----
        float rm0 = -1e30f, rm1 = -1e30f;
#pragma unroll
        for (int n = 0; n < 8; n++) {
            sa[n][0] *= 0.125f; sa[n][1] *= 0.125f;
            sa[n][2] *= 0.125f; sa[n][3] *= 0.125f;
            rm0 = fmaxf(rm0, fmaxf(sa[n][0], sa[n][1]));
            rm1 = fmaxf(rm1, fmaxf(sa[n][2], sa[n][3]));
        }
        rm0 = fmaxf(rm0, __shfl_xor_sync(0xffffffffu, rm0, 1));
        rm0 = fmaxf(rm0, __shfl_xor_sync(0xffffffffu, rm0, 2));
        rm1 = fmaxf(rm1, __shfl_xor_sync(0xffffffffu, rm1, 1));
        rm1 = fmaxf(rm1, __shfl_xor_sync(0xffffffffu, rm1, 2));

        const float nm0 = fmaxf(m0, rm0), nm1 = fmaxf(m1, rm1);
        const float c0 = __expf(m0 - nm0), c1 = __expf(m1 - nm1);
        float rs0 = 0.f, rs1 = 0.f;
#pragma unroll
        for (int n = 0; n < 8; n++) {
            float p0 = __expf(sa[n][0] - nm0);
            float p1 = __expf(sa[n][1] - nm0);
            float p2 = __expf(sa[n][2] - nm1);
            float p3 = __expf(sa[n][3] - nm1);
            rs0 += p0 + p1; rs1 += p2 + p3;
            ps[(wr + qr) * FSTR + n * 4 + qc] = h2u(p0, p1);
            ps[(wr + qr + 8) * FSTR + n * 4 + qc] = h2u(p2, p3);
            o[n][0] *= c0; o[n][1] *= c0; o[n][2] *= c1; o[n][3] *= c1;
        }
        rs0 += __shfl_xor_sync(0xffffffffu, rs0, 1);
        rs0 += __shfl_xor_sync(0xffffffffu, rs0, 2);
        rs1 += __shfl_xor_sync(0xffffffffu, rs1, 1);
        rs1 += __shfl_xor_sync(0xffffffffu, rs1, 2);
        l0 = l0 * c0 + rs0; l1 = l1 * c1 + rs1;
        m0 = nm0; m1 = nm1;

        __syncwarp();

        // ---- O += P @ V ----
#pragma unroll
        for (int k = 0; k < 4; k++) {
            uint32_t pa[4];
            pa[0] = ps[(wr + qr) * FSTR + k * 8 + qc];
            pa[1] = ps[(wr + qr + 8) * FSTR + k * 8 + qc];
            pa[2] = ps[(wr + qr) * FSTR + k * 8 + qc + 4];
            pa[3] = ps[(wr + qr + 8) * FSTR + k * 8 + qc + 4];
#pragma unroll
            for (int n = 0; n < 8; n++) {
                uint32_t bf[2];
                bf[0] = vs[(n * 8 + qr) * FSTR + k * 8 + qc];
                bf[1] = vs[(n * 8 + qr) * FSTR + k * 8 + qc + 4];
                mma_f16(o[n], pa, bf);
            }
        }
        __syncthreads();
    }

    // ---- epilogue -> half ctx ----
    const float i0 = 1.f / l0, i1 = 1.f / l1;
    __half* Og = ctx + (long)(b * SS + q0 + wr) * DD + h * DH;
#pragma unroll
    for (int n = 0; n < 8; n++) {
        *(__half2*)&Og[(long)qr * DD + n * 8 + 2 * qc] = __floats2half2_rn(o[n][0] * i0, o[n][1] * i0);
        *(__half2*)&Og[(long)(qr + 8) * DD + n * 8 + 2 * qc] = __floats2half2_rn(o[n][2] * i1, o[n][3] * i1);
    }
}

// ======================= radix-select top-k + masked softmax -> half P =======================
__global__ __launch_bounds__(256) void topk_softmax_kernel(const float* __restrict__ P,
                                                           __half* __restrict__ Ph)
{
    const long base = (long)blockIdx.x * SS;
    __shared__ float vals[SS];
    __shared__ unsigned keys[SS];
    __shared__ unsigned hist[256];
    __shared__ float redA[8], redB[8];
    __shared__ unsigned s_prefix;
    __shared__ int s_need;

    const int t = threadIdx.x;
    const int w = t >> 5, lane = t & 31;

    float lmax = -1e30f;
#pragma unroll
    for (int i = 0; i < 4; i++) {
        float v = P[base + t + i * 256];
        vals[t + i * 256] = v;
        unsigned u = __float_as_uint(v);
        u ^= (u >> 31) ? 0xFFFFFFFFu : 0x80000000u;
        keys[t + i * 256] = u;
        lmax = fmaxf(lmax, v);
    }
#pragma unroll
    for (int o = 16; o > 0; o >>= 1)
        lmax = fmaxf(lmax, __shfl_xor_sync(0xffffffffu, lmax, o));
    if (lane == 0) redA[w] = lmax;
    __syncthreads();
    float mx = redA[0];
#pragma unroll
    for (int i = 1; i < 8; i++) mx = fmaxf(mx, redA[i]);

    unsigned prefix = 0;
    int need = KSEL;
#pragma unroll
    for (int pass = 0; pass < 4; pass++) {
        const int shift = 24 - 8 * pass;
        const unsigned hmask = pass ? (0xFFFFFFFFu << (shift + 8)) : 0u;
        hist[t] = 0;
        __syncthreads();
#pragma unroll
        for (int i = 0; i < 4; i++) {
            unsigned u = keys[t + i * 256];
            if ((u & hmask) == prefix)
                atomicAdd(&hist[(u >> shift) & 0xFFu], 1u);
        }
        __syncthreads();
        if (t == 0) {
            int cum = 0, bsel = 0;
            for (int bbin = 255; bbin >= 0; bbin--) {
                int hh = (int)hist[bbin];
                if (cum + hh >= need) { bsel = bbin; break; }
                cum += hh;
            }
            s_prefix = prefix | ((unsigned)bsel << shift);
            s_need = need - cum;
        }
        __syncthreads();
        prefix = s_prefix;
        need = s_need;
        __syncthreads();
    }
    const unsigned thr = prefix;

    float e[4];
    float sk = 0.f, sf = 0.f;
#pragma unroll
    for (int i = 0; i < 4; i++) {
        float v = vals[t + i * 256];
        float ef = __expf(v - mx);
        bool kp = keys[t + i * 256] >= thr;
        e[i] = kp ? ef : 0.f;
        sk += e[i];
        sf += ef;
    }
#pragma unroll
    for (int o = 16; o > 0; o >>= 1) {
        sk += __shfl_xor_sync(0xffffffffu, sk, o);
        sf += __shfl_xor_sync(0xffffffffu, sf, o);
    }
    if (lane == 0) { redA[w] = sk; redB[w] = sf; }
    __syncthreads();
    float tk = 0.f, tf = 0.f;
#pragma unroll
    for (int i = 0; i < 8; i++) { tk += redA[i]; tf += redB[i]; }
    const float denom = tk + 1e-9f * tf;
    const float inv = 1.f / denom;
#pragma unroll
    for (int i = 0; i < 4; i++)
        Ph[base + t + i * 256] = __float2half(e[i] * inv);
}

// ======================= fuse + residual + LN1 (f32 + half outputs) =======================
__global__ __launch_bounds__(256) void fuse_ln1_kernel(
    const float* __restrict__ src, const float* __restrict__ dense,
    const float* __restrict__ sparse, const float* __restrict__ lam,
    const float* __restrict__ g, const float* __restrict__ bb,
    float* __restrict__ x, __half* __restrict__ xh)
{
    const long row = (long)blockIdx.x * DD;
    __shared__ float buf[DD];
    __shared__ float r1[8], r2[8];
    const float sig = 1.f / (1.f + __expf(-lam[0]));
    const float osig = 1.f - sig;

    float s1 = 0.f, s2 = 0.f;
    for (int d = threadIdx.x; d < DD; d += 256) {
        float v = src[row + d] + sig * dense[row + d] + osig * sparse[row + d];
        buf[d] = v; s1 += v; s2 += v * v;
    }
#pragma unroll
    for (int o = 16; o > 0; o >>= 1) {
        s1 += __shfl_xor_sync(0xffffffffu, s1, o);
        s2 += __shfl_xor_sync(0xffffffffu, s2, o);
    }
    const int w = threadIdx.x >> 5, lane = threadIdx.x & 31;
    if (lane == 0) { r1[w] = s1; r2[w] = s2; }
    __syncthreads();
    if (threadIdx.x == 0) {
        float a = 0.f, c = 0.f;
        for (int i = 0; i < 8; i++) { a += r1[i]; c += r2[i]; }
        r1[0] = a; r2[0] = c;
    }
    __syncthreads();
    const float mean = r1[0] * (1.f / DD);
    const float var = r2[0] * (1.f / DD) - mean * mean;
    const float rstd = rsqrtf(var + 1e-5f);
    for (int d = threadIdx.x; d < DD; d += 256) {
        float v = (buf[d] - mean) * rstd * g[d] + bb[d];
        x[row + d] = v;
        xh[row + d] = __float2half(v);
    }
}

// ======================= residual + LN2 -> out =======================
__global__ __launch_bounds__(256) void ln2_kernel(
    const float* __restrict__ x, const float* __restrict__ ff,
    const float* __restrict__ g, const float* __restrict__ bb,
    float* __restrict__ out)
{
    const long row = (long)blockIdx.x * DD;
    __shared__ float buf[DD];
    __shared__ float r1[8], r2[8];

    float s1 = 0.f, s2 = 0.f;
    for (int d = threadIdx.x; d < DD; d += 256) {
        float v = x[row + d] + ff[row + d];
        buf[d] = v; s1 += v; s2 += v * v;
    }
#pragma unroll
    for (int o = 16; o > 0; o >>= 1) {
        s1 += __shfl_xor_sync(0xffffffffu, s1, o);
        s2 += __shfl_xor_sync(0xffffffffu, s2, o);
    }
    const int w = threadIdx.x >> 5, lane = threadIdx.x & 31;
    if (lane == 0) { r1[w] = s1; r2[w] = s2; }
    __syncthreads();
    if (threadIdx.x == 0) {
        float a = 0.f, c = 0.f;
        for (int i = 0; i < 8; i++) { a += r1[i]; c += r2[i]; }
        r1[0] = a; r2[0] = c;
    }
    __syncthreads();
    const float mean = r1[0] * (1.f / DD);
    const float var = r2[0] * (1.f / DD) - mean * mean;
    const float rstd = rsqrtf(var + 1e-5f);
    for (int d = threadIdx.x; d < DD; d += 256)
        out[row + d] = (buf[d] - mean) * rstd * g[d] + bb[d];
}

// ======================= launch =======================
extern "C" void kernel_launch(void* const* d_in, const int* in_sizes, int n_in,
                              void* d_out, int out_size)
{
    (void)in_sizes; (void)n_in; (void)out_size;
    const float* src    = (const float*)d_in[0];
    const float* in_w   = (const float*)d_in[1];
    const float* in_b   = (const float*)d_in[2];
    const float* outp_w = (const float*)d_in[3];
    const float* outp_b = (const float*)d_in[4];
    const float* Qp_w   = (const float*)d_in[5];
    const float* Qp_b   = (const float*)d_in[6];
    const float* Kp_w   = (const float*)d_in[7];
    const float* Kp_b   = (const float*)d_in[8];
    const float* Vp_w   = (const float*)d_in[9];
    const float* Vp_b   = (const float*)d_in[10];
    const float* lam    = (const float*)d_in[11];
    const float* ff1_w  = (const float*)d_in[12];
    const float* ff1_b  = (const float*)d_in[13];
    const float* ff2_w  = (const float*)d_in[14];
    const float* ff2_b  = (const float*)d_in[15];
    const float* ln1_g  = (const float*)d_in[16];
    const float* ln1_b  = (const float*)d_in[17];
    const float* ln2_g  = (const float*)d_in[18];
    const float* ln2_b  = (const float*)d_in[19];
    float* out = (float*)d_out;

    __half *hw_in, *hw_out, *hw_Qp, *hw_Kp, *hw_Vp, *hw_f1, *hw_f2;
    __half *src_h, *qkv_h, *ctx_h, *Qlr_h, *Klr_h, *Vlr_h, *Vt_h, *Ph, *x_h, *h1_h;
    float *P, *dense, *sparse, *x, *ff;
    cudaGetSymbolAddress((void**)&hw_in,  g_hw_in);
    cudaGetSymbolAddress((void**)&hw_out, g_hw_out);
    cudaGetSymbolAddress((void**)&hw_Qp,  g_hw_Qp);
    cudaGetSymbolAddress((void**)&hw_Kp,  g_hw_Kp);
    cudaGetSymbolAddress((void**)&hw_Vp,  g_hw_Vp);
    cudaGetSymbolAddress((void**)&hw_f1,  g_hw_f1);
    cudaGetSymbolAddress((void**)&hw_f2,  g_hw_f2);
    cudaGetSymbolAddress((void**)&src_h,  g_src_h);
    cudaGetSymbolAddress((void**)&qkv_h,  g_qkv_h);
    cudaGetSymbolAddress((void**)&ctx_h,  g_ctx_h);
    cudaGetSymbolAddress((void**)&Qlr_h,  g_Qlr_h);
    cudaGetSymbolAddress((void**)&Klr_h,  g_Klr_h);
    cudaGetSymbolAddress((void**)&Vlr_h,  g_Vlr_h);
    cudaGetSymbolAddress((void**)&Vt_h,   g_Vt_h);
    cudaGetSymbolAddress((void**)&Ph,     g_Ph);
    cudaGetSymbolAddress((void**)&x_h,    g_x_h);
    cudaGetSymbolAddress((void**)&h1_h,   g_h1_h);
    cudaGetSymbolAddress((void**)&P,      g_P);
    cudaGetSymbolAddress((void**)&dense,  g_dense);
    cudaGetSymbolAddress((void**)&sparse, g_sparse);
    cudaGetSymbolAddress((void**)&x,      g_x);
    cudaGetSymbolAddress((void**)&ff,     g_ff);

    // 0. convert weights + src to half
    f2h_kernel<<<(3 * DD * DD) / 1024, 256>>>(in_w, hw_in, 3 * DD * DD);
    f2h_kernel<<<(DD * DD) / 1024, 256>>>(outp_w, hw_out, DD * DD);
    f2h_kernel<<<(RR * DD) / 1024, 256>>>(Qp_w, hw_Qp, RR * DD);
    f2h_kernel<<<(RR * DD) / 1024, 256>>>(Kp_w, hw_Kp, RR * DD);
    f2h_kernel<<<(DD * DD) / 1024, 256>>>(Vp_w, hw_Vp, DD * DD);
    f2h_kernel<<<(DFFN * DD) / 1024, 256>>>(ff1_w, hw_f1, DFFN * DD);
    f2h_kernel<<<(DD * DFFN) / 1024, 256>>>(ff2_w, hw_f2, DD * DFFN);
    f2h_kernel<<<(NTOK * DD) / 1024, 256>>>(src, src_h, NTOK * DD);

    // 1. qkv = src @ in_proj^T + b  -> half
    hgemm_nt<<<dim3(3 * DD / BN, NTOK / BM), 256>>>(
        src_h, hw_in, in_b, qkv_h, 3 * DD, DD, 0, 0, 0, 1.f, 0, 1);
    // 2. dense attention -> half ctx
    flash_attn_kernel<<<dim3(SS / 128, HH, BB), 256>>>(qkv_h, ctx_h);
    // 3. dense = ctx @ out_proj^T + b  -> f32
    hgemm_nt<<<dim3(DD / BN, NTOK / BM), 256>>>(
        ctx_h, hw_out, outp_b, dense, DD, DD, 0, 0, 0, 1.f, 0, 0);
    // 4-6. low-rank projections -> half
    hgemm_nt<<<dim3(1, NTOK / BM), 256>>>(
        src_h, hw_Qp, Qp_b, Qlr_h, RR, DD, 0, 0, 0, 1.f, 0, 1);
    hgemm_nt<<<dim3(1, NTOK / BM), 256>>>(
        src_h, hw_Kp, Kp_b, Klr_h, RR, DD, 0, 0, 0, 1.f, 0, 1);
    hgemm_nt<<<dim3(DD / BN, NTOK / BM), 256>>>(
        src_h, hw_Vp, Vp_b, Vlr_h, DD, DD, 0, 0, 0, 1.f, 0, 1);
    // 7. P = (Q @ K^T)/sqrt(R) per batch -> f32 scores
    hgemm_nt<<<dim3(SS / BN, SS / BM, BB), 256>>>(
        Qlr_h, Klr_h, nullptr, P, SS, RR,
        (long)SS * RR, (long)SS * RR, (long)SS * SS, 0.125f, 0, 0);
    // 8. radix top-k + masked softmax -> half P
    topk_softmax_kernel<<<NTOK, 256>>>(P, Ph);
    // 9a. Vt = V^T per batch (half)
    transpose_h_kernel<<<dim3(SS / 32, DD / 32, BB), 256>>>(Vlr_h, Vt_h);
    // 9b. sparse = P @ Vt^T per batch -> f32
    hgemm_nt<<<dim3(DD / BN, SS / BM, BB), 256>>>(
        Ph, Vt_h, nullptr, sparse, DD, SS,
        (long)SS * SS, (long)SS * DD, (long)SS * DD, 1.f, 0, 0);
    // 10. x = LN1(src + sig*dense + (1-sig)*sparse) -> f32 + half
    fuse_ln1_kernel<<<NTOK, 256>>>(src, dense, sparse, lam, ln1_g, ln1_b, x, x_h);
    // 11. h1 = relu(x @ ff1^T + b) -> half
    hgemm_nt<<<dim3(DFFN / BN, NTOK / BM), 256>>>(
        x_h, hw_f1, ff1_b, h1_h, DFFN, DD, 0, 0, 0, 1.f, 1, 1);
    // 12. ff = h1 @ ff2^T + b -> f32
    hgemm_nt<<<dim3(DD / BN, NTOK / BM), 256>>>(
        h1_h, hw_f2, ff2_b, ff, DD, DFFN, 0, 0, 0, 1.f, 0, 0);
    // 13. out = LN2(x + ff)
    ln2_kernel<<<NTOK, 256>>>(x, ff, ln2_g, ln2_b, out);
}

// round 6
// speedup vs baseline: 5.8968x; 1.1140x over previous
#include <cuda_runtime.h>
#include <cuda_fp16.h>
#include <cstdint>
#include <math.h>

// Problem dims
#define BB   4
#define SS   1024
#define DD   1024
#define HH   16
#define DH   64
#define RR   64
#define DFFN 4096
#define NTOK (BB*SS)       // 4096
#define KSEL 204           // int(1024*0.2)

// ---------------- scratch (device globals) ----------------
__device__ __half g_hw_in[(long)3 * DD * DD];
__device__ __half g_hw_out[(long)DD * DD];
__device__ __half g_hw_Vp[(long)DD * DD];
__device__ __half g_hw_f1[(long)DFFN * DD];
__device__ __half g_hw_f2[(long)DD * DFFN];
__device__ __half g_hw_QK[2 * RR * DD];          // packed [Qp_w; Kp_w]
__device__ float  g_bias_QK[2 * RR];
__device__ __half g_src_h[(long)NTOK * DD];
__device__ __half g_qkv_h[(long)NTOK * 3 * DD];
__device__ __half g_ctx_h[(long)NTOK * DD];
__device__ __half g_QKlr_h[(long)NTOK * 2 * RR]; // [tok][128] : Q | K
__device__ __half g_Vlr_h[(long)NTOK * DD];
__device__ __half g_Vt_h[(long)NTOK * DD];
__device__ __half g_Ph[(long)BB * SS * SS];
__device__ __half g_x_h[(long)NTOK * DD];
__device__ __half g_h1_h[(long)NTOK * DFFN];
__device__ float g_P[(long)BB * SS * SS];
__device__ float g_dense[(long)NTOK * DD];
__device__ float g_sparse[(long)NTOK * DD];
__device__ float g_x[(long)NTOK * DD];
__device__ float g_ff[(long)NTOK * DD];

// ======================= helpers =======================
__device__ __forceinline__ uint32_t smem_u32(const void* p) {
    uint32_t a;
    asm("{ .reg .u64 t; cvta.to.shared.u64 t, %1; cvt.u32.u64 %0, t; }" : "=r"(a) : "l"(p));
    return a;
}
__device__ __forceinline__ void cp16(uint32_t saddr, const void* g) {
    asm volatile("cp.async.ca.shared.global [%0], [%1], 16;"
                 :: "r"(saddr), "l"(g) : "memory");
}
#define CP_COMMIT() asm volatile("cp.async.commit_group;" ::: "memory")
#define CP_WAIT2()  asm volatile("cp.async.wait_group 2;" ::: "memory")
#define CP_WAIT1()  asm volatile("cp.async.wait_group 1;" ::: "memory")
#define CP_WAIT0()  asm volatile("cp.async.wait_group 0;" ::: "memory")

__device__ __forceinline__ void mma_f16(float* c, const uint32_t* a, const uint32_t* b) {
    asm volatile(
        "mma.sync.aligned.m16n8k16.row.col.f32.f16.f16.f32 "
        "{%0,%1,%2,%3}, {%4,%5,%6,%7}, {%8,%9}, {%0,%1,%2,%3};"
        : "+f"(c[0]), "+f"(c[1]), "+f"(c[2]), "+f"(c[3])
        : "r"(a[0]), "r"(a[1]), "r"(a[2]), "r"(a[3]), "r"(b[0]), "r"(b[1]));
}
__device__ __forceinline__ void ldsm_x4(uint32_t* r, uint32_t saddr) {
    asm volatile("ldmatrix.sync.aligned.m8n8.x4.shared.b16 {%0,%1,%2,%3}, [%4];"
                 : "=r"(r[0]), "=r"(r[1]), "=r"(r[2]), "=r"(r[3]) : "r"(saddr));
}
__device__ __forceinline__ void ldsm_x2(uint32_t* r, uint32_t saddr) {
    asm volatile("ldmatrix.sync.aligned.m8n8.x2.shared.b16 {%0,%1}, [%2];"
                 : "=r"(r[0]), "=r"(r[1]) : "r"(saddr));
}
__device__ __forceinline__ uint32_t h2u(float x, float y) {
    __half2 h = __floats2half2_rn(x, y);
    return *(uint32_t*)&h;
}

// ======================= fused converter (all weights + src + packed QK) =======================
// block = 1024 elems. Segments in blocks:
// [0,3072) in_w | [3072,4096) outp | [4096,5120) Vp | [5120,9216) ff1
// [9216,13312) ff2 | [13312,17408) src | [17408,17472) Qp->QK | [17472,17536) Kp->QK+ | 17536: bias
__global__ __launch_bounds__(256) void convert_all(
    const float* in_w, const float* outp_w, const float* Vp_w,
    const float* ff1_w, const float* ff2_w, const float* src,
    const float* Qp_w, const float* Kp_w, const float* Qp_b, const float* Kp_b,
    __half* hw_in, __half* hw_out, __half* hw_Vp, __half* hw_f1, __half* hw_f2,
    __half* src_h, __half* hw_QK, float* bias_QK)
{
    const int bid = blockIdx.x, t = threadIdx.x;
    if (bid == 17536) {
        if (t < RR) bias_QK[t] = Qp_b[t];
        else if (t < 2 * RR) bias_QK[t] = Kp_b[t - RR];
        return;
    }
    const float* in; __half* out; long off;
    if      (bid < 3072)  { in = in_w;  out = hw_in;  off = (long)bid * 1024; }
    else if (bid < 4096)  { in = outp_w; out = hw_out; off = (long)(bid - 3072) * 1024; }
    else if (bid < 5120)  { in = Vp_w;  out = hw_Vp;  off = (long)(bid - 4096) * 1024; }
    else if (bid < 9216)  { in = ff1_w; out = hw_f1;  off = (long)(bid - 5120) * 1024; }
    else if (bid < 13312) { in = ff2_w; out = hw_f2;  off = (long)(bid - 9216) * 1024; }
    else if (bid < 17408) { in = src;   out = src_h;  off = (long)(bid - 13312) * 1024; }
    else if (bid < 17472) { in = Qp_w;  out = hw_QK;  off = (long)(bid - 17408) * 1024; }
    else                  { in = Kp_w;  out = hw_QK + (long)RR * DD; off = (long)(bid - 17472) * 1024; }
    long i = off + t * 4;
    float4 v = *(const float4*)(in + i);
    *(__half2*)(out + i) = __floats2half2_rn(v.x, v.y);
    *(__half2*)(out + i + 2) = __floats2half2_rn(v.z, v.w);
}

// ======================= fp16 warp-MMA GEMM (ldmatrix + 3-stage cp.async) =======================
// C = alpha * A(MxK, lda) * B^T(NxK, ldb) + bias ; CTA 128x128x32h, 8 warps (2x4), warp 64x32.
#define BM 128
#define BN 128
#define BKH 32     // halves per K chunk
#define KSTRH 20   // b32 row stride (16 data + 4 pad)
#define TILE_B32 (BM * KSTRH)
#define GEMM_SMEM (3 * 2 * TILE_B32 * 4)

__global__ __launch_bounds__(256) void hgemm_nt(
    const __half* __restrict__ A, const __half* __restrict__ B,
    const float* __restrict__ bias, void* __restrict__ Cout,
    int N, int K, int lda, int ldb,
    long sA, long sB, long sC, float alpha, int relu, int out_half)
{
    extern __shared__ uint32_t gsm[];
    uint32_t* Asm = gsm;                  // 3 stages
    uint32_t* Bsm = gsm + 3 * TILE_B32;

    A += (long)blockIdx.z * sA;
    B += (long)blockIdx.z * sB;

    const int t = threadIdx.x;
    const int wid = t >> 5, l = t & 31;
    const int wm = wid >> 2, wn = wid & 3;
    const int mbase = wm * 64, nbase = wn * 32;
    const int qr = l >> 2, qc = l & 3;
    const int row0 = blockIdx.y * BM, col0 = blockIdx.x * BN;

    const uint32_t sA0 = smem_u32(Asm);
    const uint32_t sB0 = smem_u32(Bsm);

    const int lr = t >> 2;            // 0..63
    const int lc4 = (t & 3) * 4;      // b32 col

    // ldmatrix lane addresses (stage 0 bases, byte offsets)
    const uint32_t a_lm = sA0 + (uint32_t)(((mbase + (l & 15)) * KSTRH + (l >> 4) * 4) * 4);
    const uint32_t b_lm = sB0 + (uint32_t)(((nbase + (l & 7)) * KSTRH + ((l >> 3) & 1) * 4) * 4);

    float acc[4][4][4];
#pragma unroll
    for (int i = 0; i < 4; i++)
#pragma unroll
        for (int j = 0; j < 4; j++)
#pragma unroll
            for (int q = 0; q < 4; q++) acc[i][j][q] = 0.f;

    const int nc = K / BKH;

    auto prefetch = [&](int cc) {
        const int st = cc % 3;
        const int k0 = cc * BKH;
        const uint32_t sAs = sA0 + st * TILE_B32 * 4;
        const uint32_t sBs = sB0 + st * TILE_B32 * 4;
#pragma unroll
        for (int j = 0; j < 2; j++) {
            int m = lr + j * 64;
            cp16(sAs + (m * KSTRH + lc4) * 4, &A[(long)(row0 + m) * lda + k0 + lc4 * 2]);
        }
#pragma unroll
        for (int j = 0; j < 2; j++) {
            int n = lr + j * 64;
            cp16(sBs + (n * KSTRH + lc4) * 4, &B[(long)(col0 + n) * ldb + k0 + lc4 * 2]);
        }
        CP_COMMIT();
    };

    prefetch(0);
    if (nc > 1) prefetch(1);

    for (int c = 0; c < nc; c++) {
        if (c + 2 < nc) { prefetch(c + 2); CP_WAIT2(); }
        else if (c + 1 < nc) { CP_WAIT1(); }
        else { CP_WAIT0(); }
        __syncthreads();

        const uint32_t stoff = (uint32_t)((c % 3) * TILE_B32 * 4);
#pragma unroll
        for (int kk = 0; kk < 2; kk++) {
            const uint32_t koff = stoff + kk * 8 * 4;
            uint32_t af[4][4], bf[4][2];
#pragma unroll
            for (int mt = 0; mt < 4; mt++)
                ldsm_x4(af[mt], a_lm + koff + mt * 16 * KSTRH * 4);
#pragma unroll
            for (int nt = 0; nt < 4; nt++)
                ldsm_x2(bf[nt], b_lm + koff + nt * 8 * KSTRH * 4);
#pragma unroll
            for (int mt = 0; mt < 4; mt++)
#pragma unroll
                for (int nt = 0; nt < 4; nt++)
                    mma_f16(acc[mt][nt], af[mt], bf[nt]);
        }
        __syncthreads();
    }

    // ---- epilogue ----
#pragma unroll
    for (int mt = 0; mt < 4; mt++) {
        const int r = row0 + mbase + mt * 16 + qr;
#pragma unroll
        for (int nt = 0; nt < 4; nt++) {
            const int cc = col0 + nbase + nt * 8 + qc * 2;
            float b0 = 0.f, b1 = 0.f;
            if (bias) { b0 = bias[cc]; b1 = bias[cc + 1]; }
            float v0 = acc[mt][nt][0] * alpha + b0;
            float v1 = acc[mt][nt][1] * alpha + b1;
            float v2 = acc[mt][nt][2] * alpha + b0;
            float v3 = acc[mt][nt][3] * alpha + b1;
            if (relu) {
                v0 = fmaxf(v0, 0.f); v1 = fmaxf(v1, 0.f);
                v2 = fmaxf(v2, 0.f); v3 = fmaxf(v3, 0.f);
            }
            if (out_half) {
                __half* C = (__half*)Cout + blockIdx.z * sC;
                *(__half2*)&C[(long)r * N + cc] = __floats2half2_rn(v0, v1);
                *(__half2*)&C[(long)(r + 8) * N + cc] = __floats2half2_rn(v2, v3);
            } else {
                float* C = (float*)Cout + blockIdx.z * sC;
                float2 p0 = {v0, v1}, p1 = {v2, v3};
                *(float2*)&C[(long)r * N + cc] = p0;
                *(float2*)&C[(long)(r + 8) * N + cc] = p1;
            }
        }
    }
}

// ======================= half transpose: Vt[b][d][s] = V[b][s][d] =======================
__global__ __launch_bounds__(256) void transpose_h_kernel(const __half* __restrict__ V,
                                                          __half* __restrict__ Vt)
{
    __shared__ __half tile[32][33];
    const __half* Vb = V + (long)blockIdx.z * SS * DD;
    __half* Vtb = Vt + (long)blockIdx.z * SS * DD;
    const int s0 = blockIdx.x * 32, d0 = blockIdx.y * 32;
    const int tx = threadIdx.x & 31, ty0 = threadIdx.x >> 5;
#pragma unroll
    for (int i = 0; i < 4; i++) {
        int ty = ty0 + i * 8;
        tile[ty][tx] = Vb[(long)(s0 + ty) * DD + d0 + tx];
    }
    __syncthreads();
#pragma unroll
    for (int i = 0; i < 4; i++) {
        int ty = ty0 + i * 8;
        Vtb[(long)(d0 + ty) * SS + s0 + tx] = tile[tx][ty];
    }
}

// ======================= dense MHA: fp16 tensor-core flash attention =======================
#define FSTR 36   // b32 row stride

__global__ __launch_bounds__(256) void flash_attn_kernel(const __half* __restrict__ qkv,
                                                         __half* __restrict__ ctx)
{
    __shared__ uint32_t ps[128 * FSTR];
    __shared__ uint32_t ks[64 * FSTR];
    __shared__ uint32_t vs[64 * FSTR];
    __half* vs_h = (__half*)vs;

    const int t = threadIdx.x, w = t >> 5, l = t & 31;
    const int qr = l >> 2, qc = l & 3;
    const int q0 = blockIdx.x * 128, h = blockIdx.y, b = blockIdx.z;
    const int wr = w * 16;

    const __half* Qg = qkv + (long)(b * SS + q0) * (3 * DD) + h * DH;
    const __half* Kg = qkv + (long)(b * SS) * (3 * DD) + DD + h * DH;
    const __half* Vg = qkv + (long)(b * SS) * (3 * DD) + 2 * DD + h * DH;

#pragma unroll
    for (int i = 0; i < 4; i++) {
        int idx = t + i * 256;
        int r = idx >> 3, c16 = idx & 7;
        float4 v = *(const float4*)(Qg + (long)r * (3 * DD) + c16 * 8);
        *(float4*)&ps[r * FSTR + c16 * 4] = v;
    }
    __syncthreads();
    uint32_t qa[4][4];
#pragma unroll
    for (int k = 0; k < 4; k++) {
        qa[k][0] = ps[(wr + qr) * FSTR + k * 8 + qc];
        qa[k][1] = ps[(wr + qr + 8) * FSTR + k * 8 + qc];
        qa[k][2] = ps[(wr + qr) * FSTR + k * 8 + qc + 4];
        qa[k][3] = ps[(wr + qr + 8) * FSTR + k * 8 + qc + 4];
    }
    __syncthreads();

    float m0 = -1e30f, m1 = -1e30f, l0 = 0.f, l1 = 0.f;
    float o[8][4];
#pragma unroll
    for (int n = 0; n < 8; n++)
#pragma unroll
        for (int i = 0; i < 4; i++) o[n][i] = 0.f;

    for (int kt = 0; kt < SS; kt += 64) {
#pragma unroll
        for (int i = 0; i < 2; i++) {
            int idx = t + i * 256;
            int r = idx >> 3, c16 = idx & 7;
            float4 kv = *(const float4*)(Kg + (long)(kt + r) * (3 * DD) + c16 * 8);
            *(float4*)&ks[r * FSTR + c16 * 4] = kv;
            float4 vv = *(const float4*)(Vg + (long)(kt + r) * (3 * DD) + c16 * 8);
            const __half* vh = (const __half*)&vv;
#pragma unroll
            for (int j = 0; j < 8; j++)
                vs_h[(c16 * 8 + j) * (2 * FSTR) + r] = vh[j];
        }
        __syncthreads();

        float sa[8][4];
#pragma unroll
        for (int n = 0; n < 8; n++)
#pragma unroll
            for (int i = 0; i < 4; i++) sa[n][i] = 0.f;
#pragma unroll
        for (int k = 0; k < 4; k++) {
#pragma unroll
            for (int n = 0; n < 8; n++) {
                uint32_t bf[2];
                bf[0] = ks[(n * 8 + qr) * FSTR + k * 8 + qc];
                bf[1] = ks[(n * 8 + qr) * FSTR + k * 8 + qc + 4];
                mma_f16(sa[n], qa[k], bf);
            }
        }

        float rm0 = -1e30f, rm1 = -1e30f;
#pragma unroll
        for (int n = 0; n < 8; n++) {
            sa[n][0] *= 0.125f; sa[n][1] *= 0.125f;
            sa[n][2] *= 0.125f; sa[n][3] *= 0.125f;
            rm0 = fmaxf(rm0, fmaxf(sa[n][0], sa[n][1]));
            rm1 = fmaxf(rm1, fmaxf(sa[n][2], sa[n][3]));
        }
        rm0 = fmaxf(rm0, __shfl_xor_sync(0xffffffffu, rm0, 1));
        rm0 = fmaxf(rm0, __shfl_xor_sync(0xffffffffu, rm0, 2));
        rm1 = fmaxf(rm1, __shfl_xor_sync(0xffffffffu, rm1, 1));
        rm1 = fmaxf(rm1, __shfl_xor_sync(0xffffffffu, rm1, 2));

        const float nm0 = fmaxf(m0, rm0), nm1 = fmaxf(m1, rm1);
        const float c0 = __expf(m0 - nm0), c1 = __expf(m1 - nm1);
        float rs0 = 0.f, rs1 = 0.f;
#pragma unroll
        for (int n = 0; n < 8; n++) {
            float p0 = __expf(sa[n][0] - nm0);
            float p1 = __expf(sa[n][1] - nm0);
            float p2 = __expf(sa[n][2] - nm1);
            float p3 = __expf(sa[n][3] - nm1);
            rs0 += p0 + p1; rs1 += p2 + p3;
            ps[(wr + qr) * FSTR + n * 4 + qc] = h2u(p0, p1);
            ps[(wr + qr + 8) * FSTR + n * 4 + qc] = h2u(p2, p3);
            o[n][0] *= c0; o[n][1] *= c0; o[n][2] *= c1; o[n][3] *= c1;
        }
        rs0 += __shfl_xor_sync(0xffffffffu, rs0, 1);
        rs0 += __shfl_xor_sync(0xffffffffu, rs0, 2);
        rs1 += __shfl_xor_sync(0xffffffffu, rs1, 1);
        rs1 += __shfl_xor_sync(0xffffffffu, rs1, 2);
        l0 = l0 * c0 + rs0; l1 = l1 * c1 + rs1;
        m0 = nm0; m1 = nm1;

        __syncwarp();

#pragma unroll
        for (int k = 0; k < 4; k++) {
            uint32_t pa[4];
            pa[0] = ps[(wr + qr) * FSTR + k * 8 + qc];
            pa[1] = ps[(wr + qr + 8) * FSTR + k * 8 + qc];
            pa[2] = ps[(wr + qr) * FSTR + k * 8 + qc + 4];
            pa[3] = ps[(wr + qr + 8) * FSTR + k * 8 + qc + 4];
#pragma unroll
            for (int n = 0; n < 8; n++) {
                uint32_t bf[2];
                bf[0] = vs[(n * 8 + qr) * FSTR + k * 8 + qc];
                bf[1] = vs[(n * 8 + qr) * FSTR + k * 8 + qc + 4];
                mma_f16(o[n], pa, bf);
            }
        }
        __syncthreads();
    }

    const float i0 = 1.f / l0, i1 = 1.f / l1;
    __half* Og = ctx + (long)(b * SS + q0 + wr) * DD + h * DH;
#pragma unroll
    for (int n = 0; n < 8; n++) {
        *(__half2*)&Og[(long)qr * DD + n * 8 + 2 * qc] = __floats2half2_rn(o[n][0] * i0, o[n][1] * i0);
        *(__half2*)&Og[(long)(qr + 8) * DD + n * 8 + 2 * qc] = __floats2half2_rn(o[n][2] * i1, o[n][3] * i1);
    }
}

// ======================= radix-select top-k + masked softmax -> half P =======================
__global__ __launch_bounds__(256) void topk_softmax_kernel(const float* __restrict__ P,
                                                           __half* __restrict__ Ph)
{
    const long base = (long)blockIdx.x * SS;
    __shared__ float vals[SS];
    __shared__ unsigned keys[SS];
    __shared__ unsigned hist[256];
    __shared__ float redA[8], redB[8];
    __shared__ unsigned s_prefix;
    __shared__ int s_need;

    const int t = threadIdx.x;
    const int w = t >> 5, lane = t & 31;

    float lmax = -1e30f;
#pragma unroll
    for (int i = 0; i < 4; i++) {
        float v = P[base + t + i * 256];
        vals[t + i * 256] = v;
        unsigned u = __float_as_uint(v);
        u ^= (u >> 31) ? 0xFFFFFFFFu : 0x80000000u;
        keys[t + i * 256] = u;
        lmax = fmaxf(lmax, v);
    }
#pragma unroll
    for (int o = 16; o > 0; o >>= 1)
        lmax = fmaxf(lmax, __shfl_xor_sync(0xffffffffu, lmax, o));
    if (lane == 0) redA[w] = lmax;
    __syncthreads();
    float mx = redA[0];
#pragma unroll
    for (int i = 1; i < 8; i++) mx = fmaxf(mx, redA[i]);

    unsigned prefix = 0;
    int need = KSEL;
#pragma unroll
    for (int pass = 0; pass < 4; pass++) {
        const int shift = 24 - 8 * pass;
        const unsigned hmask = pass ? (0xFFFFFFFFu << (shift + 8)) : 0u;
        hist[t] = 0;
        __syncthreads();
#pragma unroll
        for (int i = 0; i < 4; i++) {
            unsigned u = keys[t + i * 256];
            if ((u & hmask) == prefix)
                atomicAdd(&hist[(u >> shift) & 0xFFu], 1u);
        }
        __syncthreads();
        if (t == 0) {
            int cum = 0, bsel = 0;
            for (int bbin = 255; bbin >= 0; bbin--) {
                int hh = (int)hist[bbin];
                if (cum + hh >= need) { bsel = bbin; break; }
                cum += hh;
            }
            s_prefix = prefix | ((unsigned)bsel << shift);
            s_need = need - cum;
        }
        __syncthreads();
        prefix = s_prefix;
        need = s_need;
        __syncthreads();
    }
    const unsigned thr = prefix;

    float e[4];
    float sk = 0.f, sf = 0.f;
#pragma unroll
    for (int i = 0; i < 4; i++) {
        float v = vals[t + i * 256];
        float ef = __expf(v - mx);
        bool kp = keys[t + i * 256] >= thr;
        e[i] = kp ? ef : 0.f;
        sk += e[i];
        sf += ef;
    }
#pragma unroll
    for (int o = 16; o > 0; o >>= 1) {
        sk += __shfl_xor_sync(0xffffffffu, sk, o);
        sf += __shfl_xor_sync(0xffffffffu, sf, o);
    }
    if (lane == 0) { redA[w] = sk; redB[w] = sf; }
    __syncthreads();
    float tk = 0.f, tf = 0.f;
#pragma unroll
    for (int i = 0; i < 8; i++) { tk += redA[i]; tf += redB[i]; }
    const float inv = 1.f / (tk + 1e-9f * tf);
#pragma unroll
    for (int i = 0; i < 4; i++)
        Ph[base + t + i * 256] = __float2half(e[i] * inv);
}

// ======================= fuse + residual + LN1 =======================
__global__ __launch_bounds__(256) void fuse_ln1_kernel(
    const float* __restrict__ src, const float* __restrict__ dense,
    const float* __restrict__ sparse, const float* __restrict__ lam,
    const float* __restrict__ g, const float* __restrict__ bb,
    float* __restrict__ x, __half* __restrict__ xh)
{
    const long row = (long)blockIdx.x * DD;
    __shared__ float buf[DD];
    __shared__ float r1[8], r2[8];
    const float sig = 1.f / (1.f + __expf(-lam[0]));
    const float osig = 1.f - sig;

    float s1 = 0.f, s2 = 0.f;
    for (int d = threadIdx.x; d < DD; d += 256) {
        float v = src[row + d] + sig * dense[row + d] + osig * sparse[row + d];
        buf[d] = v; s1 += v; s2 += v * v;
    }
#pragma unroll
    for (int o = 16; o > 0; o >>= 1) {
        s1 += __shfl_xor_sync(0xffffffffu, s1, o);
        s2 += __shfl_xor_sync(0xffffffffu, s2, o);
    }
    const int w = threadIdx.x >> 5, lane = threadIdx.x & 31;
    if (lane == 0) { r1[w] = s1; r2[w] = s2; }
    __syncthreads();
    if (threadIdx.x == 0) {
        float a = 0.f, c = 0.f;
        for (int i = 0; i < 8; i++) { a += r1[i]; c += r2[i]; }
        r1[0] = a; r2[0] = c;
    }
    __syncthreads();
    const float mean = r1[0] * (1.f / DD);
    const float var = r2[0] * (1.f / DD) - mean * mean;
    const float rstd = rsqrtf(var + 1e-5f);
    for (int d = threadIdx.x; d < DD; d += 256) {
        float v = (buf[d] - mean) * rstd * g[d] + bb[d];
        x[row + d] = v;
        xh[row + d] = __float2half(v);
    }
}

// ======================= residual + LN2 -> out =======================
__global__ __launch_bounds__(256) void ln2_kernel(
    const float* __restrict__ x, const float* __restrict__ ff,
    const float* __restrict__ g, const float* __restrict__ bb,
    float* __restrict__ out)
{
    const long row = (long)blockIdx.x * DD;
    __shared__ float buf[DD];
    __shared__ float r1[8], r2[8];

    float s1 = 0.f, s2 = 0.f;
    for (int d = threadIdx.x; d < DD; d += 256) {
        float v = x[row + d] + ff[row + d];
        buf[d] = v; s1 += v; s2 += v * v;
    }
#pragma unroll
    for (int o = 16; o > 0; o >>= 1) {
        s1 += __shfl_xor_sync(0xffffffffu, s1, o);
        s2 += __shfl_xor_sync(0xffffffffu, s2, o);
    }
    const int w = threadIdx.x >> 5, lane = threadIdx.x & 31;
    if (lane == 0) { r1[w] = s1; r2[w] = s2; }
    __syncthreads();
    if (threadIdx.x == 0) {
        float a = 0.f, c = 0.f;
        for (int i = 0; i < 8; i++) { a += r1[i]; c += r2[i]; }
        r1[0] = a; r2[0] = c;
    }
    __syncthreads();
    const float mean = r1[0] * (1.f / DD);
    const float var = r2[0] * (1.f / DD) - mean * mean;
    const float rstd = rsqrtf(var + 1e-5f);
    for (int d = threadIdx.x; d < DD; d += 256)
        out[row + d] = (buf[d] - mean) * rstd * g[d] + bb[d];
}

// ======================= launch =======================
extern "C" void kernel_launch(void* const* d_in, const int* in_sizes, int n_in,
                              void* d_out, int out_size)
{
    (void)in_sizes; (void)n_in; (void)out_size;
    const float* src    = (const float*)d_in[0];
    const float* in_w   = (const float*)d_in[1];
    const float* in_b   = (const float*)d_in[2];
    const float* outp_w = (const float*)d_in[3];
    const float* outp_b = (const float*)d_in[4];
    const float* Qp_w   = (const float*)d_in[5];
    const float* Qp_b   = (const float*)d_in[6];
    const float* Kp_w   = (const float*)d_in[7];
    const float* Kp_b   = (const float*)d_in[8];
    const float* Vp_w   = (const float*)d_in[9];
    const float* Vp_b   = (const float*)d_in[10];
    const float* lam    = (const float*)d_in[11];
    const float* ff1_w  = (const float*)d_in[12];
    const float* ff1_b  = (const float*)d_in[13];
    const float* ff2_w  = (const float*)d_in[14];
    const float* ff2_b  = (const float*)d_in[15];
    const float* ln1_g  = (const float*)d_in[16];
    const float* ln1_b  = (const float*)d_in[17];
    const float* ln2_g  = (const float*)d_in[18];
    const float* ln2_b  = (const float*)d_in[19];
    float* out = (float*)d_out;

    __half *hw_in, *hw_out, *hw_Vp, *hw_f1, *hw_f2, *hw_QK;
    __half *src_h, *qkv_h, *ctx_h, *QKlr_h, *Vlr_h, *Vt_h, *Ph, *x_h, *h1_h;
    float *bias_QK, *P, *dense, *sparse, *x, *ff;
    cudaGetSymbolAddress((void**)&hw_in,   g_hw_in);
    cudaGetSymbolAddress((void**)&hw_out,  g_hw_out);
    cudaGetSymbolAddress((void**)&hw_Vp,   g_hw_Vp);
    cudaGetSymbolAddress((void**)&hw_f1,   g_hw_f1);
    cudaGetSymbolAddress((void**)&hw_f2,   g_hw_f2);
    cudaGetSymbolAddress((void**)&hw_QK,   g_hw_QK);
    cudaGetSymbolAddress((void**)&bias_QK, g_bias_QK);
    cudaGetSymbolAddress((void**)&src_h,   g_src_h);
    cudaGetSymbolAddress((void**)&qkv_h,   g_qkv_h);
    cudaGetSymbolAddress((void**)&ctx_h,   g_ctx_h);
    cudaGetSymbolAddress((void**)&QKlr_h,  g_QKlr_h);
    cudaGetSymbolAddress((void**)&Vlr_h,   g_Vlr_h);
    cudaGetSymbolAddress((void**)&Vt_h,    g_Vt_h);
    cudaGetSymbolAddress((void**)&Ph,      g_Ph);
    cudaGetSymbolAddress((void**)&x_h,     g_x_h);
    cudaGetSymbolAddress((void**)&h1_h,    g_h1_h);
    cudaGetSymbolAddress((void**)&P,       g_P);
    cudaGetSymbolAddress((void**)&dense,   g_dense);
    cudaGetSymbolAddress((void**)&sparse,  g_sparse);
    cudaGetSymbolAddress((void**)&x,       g_x);
    cudaGetSymbolAddress((void**)&ff,      g_ff);

    cudaFuncSetAttribute(hgemm_nt, cudaFuncAttributeMaxDynamicSharedMemorySize, GEMM_SMEM);

    // 0. fused conversion (weights, src, packed QK weights + bias)
    convert_all<<<17537, 256>>>(in_w, outp_w, Vp_w, ff1_w, ff2_w, src,
                                Qp_w, Kp_w, Qp_b, Kp_b,
                                hw_in, hw_out, hw_Vp, hw_f1, hw_f2,
                                src_h, hw_QK, bias_QK);

    // 1. qkv = src @ in_proj^T + b -> half
    hgemm_nt<<<dim3(3 * DD / BN, NTOK / BM), 256, GEMM_SMEM>>>(
        src_h, hw_in, in_b, qkv_h, 3 * DD, DD, DD, DD, 0, 0, 0, 1.f, 0, 1);
    // 2. dense attention -> half ctx
    flash_attn_kernel<<<dim3(SS / 128, HH, BB), 256>>>(qkv_h, ctx_h);
    // 3. dense = ctx @ out_proj^T + b -> f32
    hgemm_nt<<<dim3(DD / BN, NTOK / BM), 256, GEMM_SMEM>>>(
        ctx_h, hw_out, outp_b, dense, DD, DD, DD, DD, 0, 0, 0, 1.f, 0, 0);
    // 4. QKlr = src @ [Qp;Kp]^T + b -> half [4096,128]
    hgemm_nt<<<dim3(1, NTOK / BM), 256, GEMM_SMEM>>>(
        src_h, hw_QK, bias_QK, QKlr_h, 2 * RR, DD, DD, DD, 0, 0, 0, 1.f, 0, 1);
    // 5. Vlr = src @ Vp^T + b -> half
    hgemm_nt<<<dim3(DD / BN, NTOK / BM), 256, GEMM_SMEM>>>(
        src_h, hw_Vp, Vp_b, Vlr_h, DD, DD, DD, DD, 0, 0, 0, 1.f, 0, 1);
    // 6. P = (Q @ K^T)/sqrt(R) per batch -> f32 (A = QKlr[:, :64], B = QKlr[:, 64:], ld=128)
    hgemm_nt<<<dim3(SS / BN, SS / BM, BB), 256, GEMM_SMEM>>>(
        QKlr_h, QKlr_h + RR, nullptr, P, SS, RR, 2 * RR, 2 * RR,
        (long)SS * 2 * RR, (long)SS * 2 * RR, (long)SS * SS, 0.125f, 0, 0);
    // 7. radix top-k + masked softmax -> half P
    topk_softmax_kernel<<<NTOK, 256>>>(P, Ph);
    // 8. Vt = V^T per batch
    transpose_h_kernel<<<dim3(SS / 32, DD / 32, BB), 256>>>(Vlr_h, Vt_h);
    // 9. sparse = P @ Vt^T per batch -> f32
    hgemm_nt<<<dim3(DD / BN, SS / BM, BB), 256, GEMM_SMEM>>>(
        Ph, Vt_h, nullptr, sparse, DD, SS, SS, SS,
        (long)SS * SS, (long)SS * DD, (long)SS * DD, 1.f, 0, 0);
    // 10. x = LN1(src + sig*dense + (1-sig)*sparse) -> f32 + half
    fuse_ln1_kernel<<<NTOK, 256>>>(src, dense, sparse, lam, ln1_g, ln1_b, x, x_h);
    // 11. h1 = relu(x @ ff1^T + b) -> half
    hgemm_nt<<<dim3(DFFN / BN, NTOK / BM), 256, GEMM_SMEM>>>(
        x_h, hw_f1, ff1_b, h1_h, DFFN, DD, DD, DD, 0, 0, 0, 1.f, 1, 1);
    // 12. ff = h1 @ ff2^T + b -> f32
    hgemm_nt<<<dim3(DD / BN, NTOK / BM), 256, GEMM_SMEM>>>(
        h1_h, hw_f2, ff2_b, ff, DD, DFFN, DFFN, DFFN, 0, 0, 0, 1.f, 0, 0);
    // 13. out = LN2(x + ff)
    ln2_kernel<<<NTOK, 256>>>(x, ff, ln2_g, ln2_b, out);
}